// round 5
// baseline (speedup 1.0000x reference)
#include <cuda_runtime.h>
#include <math.h>

#define NWIN 3200
#define NEG9 -1000000000.0f

// ---------------- static scratch ----------------
__device__ float  d_c1max[NWIN*16*16*32];   // (n,ci,y,32) x-padded, x<25 valid
__device__ float  d_c1min[NWIN*16*16*32];
__device__ float  d_c2max[NWIN*32*8*12];
__device__ float  d_c2min[NWIN*32*8*12];
__device__ float  d_feat[NWIN*32];
__device__ float  d_emb [NWIN*128];
__device__ float  d_Qm  [NWIN*128];
__device__ float  d_Km  [NWIN*128];
__device__ float  d_attn[16*200*200];
__device__ float  d_adj [16*200*200];
__device__ float  d_dinv[16*200];
__device__ float  d_An  [16*200*200];
__device__ float  d_X1  [NWIN*256];
__device__ float  d_G1  [NWIN*256];
__device__ float  d_X2  [NWIN*256];
__device__ float  d_G2  [NWIN*256];
__device__ float  d_gemb[16*256];
__device__ float  d_gi  [16*768];
__device__ double d_bnsum[96];
__device__ float  d_sc1[16], d_sh1[16], d_sc2[32], d_sh2[32];

__global__ void k_init(float* out){
    int t = threadIdx.x;
    if (t < 96) d_bnsum[t] = 0.0;
    if (t == 96) out[40002] = 0.f;
}

// ---------------- fused CWT + conv1(1->16) + BN stats + raw 2x2 max/min pool ----------------
__global__ void __launch_bounds__(256) k_cwtconv1(
        const float* __restrict__ x, const float* __restrict__ wr,
        const float* __restrict__ wi, const float* __restrict__ w,
        const float* __restrict__ b){
    __shared__ float xp[112];
    __shared__ float wrs[1600], wis[1600];
    __shared__ float sp[34*52];
    __shared__ float ssum[16], ssq[16];
    int n = blockIdx.x, tid = threadIdx.x;
    if (tid < 16){ ssum[tid] = 0.f; ssq[tid] = 0.f; }
    for (int i = tid; i < 112; i += 256){
        int s = i - 24;
        xp[i] = (s >= 0 && s < 50) ? x[n*50 + s] : 0.f;
    }
    for (int i = tid; i < 1600; i += 256){ wrs[i] = wr[i]; wis[i] = wi[i]; }
    for (int i = tid; i < 34*52; i += 256) sp[i] = 0.f;
    __syncthreads();

    // ---- CWT: 7 consecutive outputs per thread ----
    {
        int f = tid >> 3, jb = (tid & 7) * 7;
        const float* a  = &wrs[f*50];
        const float* bb = &wis[f*50];
        float re[7] = {0,0,0,0,0,0,0}, im[7] = {0,0,0,0,0,0,0};
        float win[7];
        #pragma unroll
        for (int q = 0; q < 7; q++) win[q] = xp[jb + q];
        #pragma unroll
        for (int k = 0; k < 50; k++){
            float wa = a[k], wb = bb[k];
            #pragma unroll
            for (int q = 0; q < 7; q++){ re[q] += win[q]*wa; im[q] += win[q]*wb; }
            #pragma unroll
            for (int q = 0; q < 6; q++) win[q] = win[q+1];
            win[6] = xp[jb + k + 7];
        }
        #pragma unroll
        for (int q = 0; q < 7; q++){
            int j = jb + q;
            if (j < 50) sp[(f+1)*52 + (j+1)] = sqrtf(re[q]*re[q] + im[q]*im[q]);
        }
    }
    __syncthreads();

    // ---- conv1: thread = (c, ypair); 2 output rows, sliding 4-row window ----
    int c = tid >> 4, yp = tid & 15;
    float wl[9];
    #pragma unroll
    for (int k = 0; k < 9; k++) wl[k] = __ldg(&w[c*9 + k]);
    float bias = __ldg(&b[c]);
    const float* r0 = &sp[(2*yp + 0)*52];
    const float* r1 = &sp[(2*yp + 1)*52];
    const float* r2 = &sp[(2*yp + 2)*52];
    const float* r3 = &sp[(2*yp + 3)*52];
    float a0=r0[0], b0=r0[1], a1=r1[0], b1=r1[1];
    float a2=r2[0], b2=r2[1], a3=r3[0], b3=r3[1];
    float s = 0.f, sq = 0.f, pm = 0.f, pn = 0.f;
    float* omax = &d_c1max[((n*16 + c)*16 + yp)*32];
    float* omin = &d_c1min[((n*16 + c)*16 + yp)*32];
    #pragma unroll
    for (int xx = 0; xx < 50; xx++){
        float c0=r0[xx+2], c1=r1[xx+2], c2=r2[xx+2], c3=r3[xx+2];
        float o0 = bias + a0*wl[0]+b0*wl[1]+c0*wl[2]
                        + a1*wl[3]+b1*wl[4]+c1*wl[5]
                        + a2*wl[6]+b2*wl[7]+c2*wl[8];
        float o1 = bias + a1*wl[0]+b1*wl[1]+c1*wl[2]
                        + a2*wl[3]+b2*wl[4]+c2*wl[5]
                        + a3*wl[6]+b3*wl[7]+c3*wl[8];
        s += o0 + o1; sq += o0*o0 + o1*o1;
        float mx = fmaxf(o0,o1), mn = fminf(o0,o1);
        if ((xx & 1) == 0){ pm = mx; pn = mn; }
        else { omax[xx>>1] = fmaxf(pm, mx); omin[xx>>1] = fminf(pn, mn); }
        a0=b0; b0=c0; a1=b1; b1=c1; a2=b2; b2=c2; a3=b3; b3=c3;
    }
    atomicAdd(&ssum[c], s); atomicAdd(&ssq[c], sq);
    __syncthreads();
    if (tid < 16){
        atomicAdd(&d_bnsum[tid],      (double)ssum[tid]);
        atomicAdd(&d_bnsum[16 + tid], (double)ssq[tid]);
    }
}

__global__ void k_bn1fin(const float* __restrict__ g, const float* __restrict__ b){
    int c = threadIdx.x; if (c >= 16) return;
    double cnt = 5120000.0;
    double mu  = d_bnsum[c] / cnt;
    double var = d_bnsum[16 + c] / cnt - mu*mu;
    float sc = g[c] * rsqrtf((float)var + 1e-5f);
    d_sc1[c] = sc;
    d_sh1[c] = b[c] - (float)mu * sc;
}

// ---------------- conv2 (16->32): 512 thr, 1 row/thread, float2 LDS, shfl pooling ----------------
__global__ void __launch_bounds__(512, 2) k_conv2(const float* __restrict__ w,
                                                  const float* __restrict__ b){
    __shared__ float sp[16*504];     // 16 x 18 x 28 (rows padded to 28 -> 8B-aligned pairs)
    __shared__ float ssum[32], ssq[32];
    int n = blockIdx.x, tid = threadIdx.x;
    if (tid < 32){ ssum[tid] = 0.f; ssq[tid] = 0.f; }
    for (int i = tid; i < 16*504; i += 512) sp[i] = 0.f;
    __syncthreads();
    // load pooled conv1 (x-stride-32 layout) + apply BN1+relu via max/min select
    for (int i = tid; i < 8192; i += 512){
        int xx = i & 31;
        if (xx < 25){
            int y = (i >> 5) & 15, ci = i >> 9;
            float sc = d_sc1[ci], sh = d_sh1[ci];
            float mx = d_c1max[n*8192 + i], mn = d_c1min[n*8192 + i];
            float v = fmaxf(sc * (sc >= 0.f ? mx : mn) + sh, 0.f);
            sp[ci*504 + (y+1)*28 + (xx+1)] = v;
        }
    }
    __syncthreads();

    int c = tid >> 4, y = tid & 15;
    float bias = __ldg(&b[c]);
    float acc[25];
    #pragma unroll
    for (int k = 0; k < 25; k++) acc[k] = bias;
    for (int ci = 0; ci < 16; ci++){
        const float* wp = &w[(c*16 + ci)*9];
        float w0=__ldg(wp+0),w1=__ldg(wp+1),w2=__ldg(wp+2),
              w3=__ldg(wp+3),w4=__ldg(wp+4),w5=__ldg(wp+5),
              w6=__ldg(wp+6),w7=__ldg(wp+7),w8=__ldg(wp+8);
        const float* r0 = &sp[ci*504 + (y+0)*28];
        const float* r1 = &sp[ci*504 + (y+1)*28];
        const float* r2 = &sp[ci*504 + (y+2)*28];
        float a0=r0[0], b0=r0[1], a1=r1[0], b1=r1[1], a2=r2[0], b2=r2[1];
        #pragma unroll
        for (int m = 0; m < 12; m++){
            float2 c0 = *reinterpret_cast<const float2*>(&r0[2*m+2]);
            float2 c1 = *reinterpret_cast<const float2*>(&r1[2*m+2]);
            float2 c2 = *reinterpret_cast<const float2*>(&r2[2*m+2]);
            acc[2*m]   += a0*w0 + b0*w1 + c0.x*w2
                        + a1*w3 + b1*w4 + c1.x*w5
                        + a2*w6 + b2*w7 + c2.x*w8;
            acc[2*m+1] += b0*w0 + c0.x*w1 + c0.y*w2
                        + b1*w3 + c1.x*w4 + c1.y*w5
                        + b2*w6 + c2.x*w7 + c2.y*w8;
            a0=c0.x; b0=c0.y; a1=c1.x; b1=c1.y; a2=c2.x; b2=c2.y;
        }
        acc[24] += a0*w0 + b0*w1 + r0[26]*w2
                 + a1*w3 + b1*w4 + r1[26]*w5
                 + a2*w6 + b2*w7 + r2[26]*w8;
    }
    // stats
    float s = 0.f, sq = 0.f;
    #pragma unroll
    for (int k = 0; k < 25; k++){ s += acc[k]; sq += acc[k]*acc[k]; }
    atomicAdd(&ssum[c], s); atomicAdd(&ssq[c], sq);
    // 2x2 pooling: partner row lives in lane^1 (y bit0 == lane bit0)
    float* omax = &d_c2max[((n*32 + c)*8 + (y>>1))*12];
    float* omin = &d_c2min[((n*32 + c)*8 + (y>>1))*12];
    #pragma unroll
    for (int xq = 0; xq < 12; xq++){
        float m  = fmaxf(acc[2*xq], acc[2*xq+1]);
        float mn = fminf(acc[2*xq], acc[2*xq+1]);
        float mo = __shfl_xor_sync(0xffffffffu, m,  1);
        float no = __shfl_xor_sync(0xffffffffu, mn, 1);
        if ((y & 1) == 0){
            omax[xq] = fmaxf(m, mo);
            omin[xq] = fminf(mn, no);
        }
    }
    __syncthreads();
    if (tid < 32){
        atomicAdd(&d_bnsum[32 + tid], (double)ssum[tid]);
        atomicAdd(&d_bnsum[64 + tid], (double)ssq[tid]);
    }
}

__global__ void k_bn2fin(const float* __restrict__ g, const float* __restrict__ b){
    int c = threadIdx.x; if (c >= 32) return;
    double cnt = 1280000.0;
    double mu  = d_bnsum[32 + c] / cnt;
    double var = d_bnsum[64 + c] / cnt - mu*mu;
    float sc = g[c] * rsqrtf((float)var + 1e-5f);
    d_sc2[c] = sc;
    d_sh2[c] = b[c] - (float)mu * sc;
}

// ---------------- feat: BN2+relu on pooled, spatial mean -> (n,32) ----------------
__global__ void k_feat(){
    __shared__ float red[256];
    int n = blockIdx.x, tid = threadIdx.x;
    int c = tid & 31, yp = tid >> 5;
    float sc = d_sc2[c], sh = d_sh2[c];
    const float* pmax = &d_c2max[((n*32 + c)*8 + yp)*12];
    const float* pmin = &d_c2min[((n*32 + c)*8 + yp)*12];
    float s = 0.f;
    #pragma unroll
    for (int xq = 0; xq < 12; xq++){
        float v = sc >= 0.f ? pmax[xq] : pmin[xq];
        s += fmaxf(sc*v + sh, 0.f);
    }
    red[tid] = s;
    __syncthreads();
    if (tid < 32){
        float t = 0.f;
        #pragma unroll
        for (int q = 0; q < 8; q++) t += red[q*32 + tid];
        d_feat[n*32 + tid] = t * (1.f/96.f);
    }
}

// ---------------- generic tiled SGEMM (64x64x16, 4x4 micro) ----------------
template<int ACT, bool TRANSB>
__global__ void __launch_bounds__(256) k_gemm(
        const float* __restrict__ A, const float* __restrict__ B,
        const float* __restrict__ bias, float* __restrict__ C,
        int M, int N, int Kd, int sA, int sB, int sC, float scale){
    __shared__ float As[16][68];
    __shared__ float Bs[16][68];
    int bz = blockIdx.z;
    A += (long)bz*sA; B += (long)bz*sB; C += (long)bz*sC;
    int tid = threadIdx.x;
    int tx = tid & 15, ty = tid >> 4;
    int row0 = blockIdx.y*64, col0 = blockIdx.x*64;
    float acc[4][4] = {};
    for (int k0 = 0; k0 < Kd; k0 += 16){
        #pragma unroll
        for (int l = 0; l < 4; l++){
            int idx = tid + l*256;
            int m = idx >> 4, k = idx & 15;
            int gm = row0 + m, gk = k0 + k;
            As[k][m] = (gm < M && gk < Kd) ? A[gm*Kd + gk] : 0.f;
        }
        #pragma unroll
        for (int l = 0; l < 4; l++){
            int idx = tid + l*256;
            if (TRANSB){
                int nn = idx >> 4, k = idx & 15;
                int gn = col0 + nn, gk = k0 + k;
                Bs[k][nn] = (gn < N && gk < Kd) ? B[gn*Kd + gk] : 0.f;
            } else {
                int k = idx >> 6, nn = idx & 63;
                int gn = col0 + nn, gk = k0 + k;
                Bs[k][nn] = (gn < N && gk < Kd) ? B[gk*N + gn] : 0.f;
            }
        }
        __syncthreads();
        #pragma unroll
        for (int k = 0; k < 16; k++){
            float4 av = *reinterpret_cast<const float4*>(&As[k][ty*4]);
            float4 bv = *reinterpret_cast<const float4*>(&Bs[k][tx*4]);
            float a[4] = {av.x, av.y, av.z, av.w};
            float bb[4] = {bv.x, bv.y, bv.z, bv.w};
            #pragma unroll
            for (int i = 0; i < 4; i++)
                #pragma unroll
                for (int j = 0; j < 4; j++)
                    acc[i][j] += a[i]*bb[j];
        }
        __syncthreads();
    }
    #pragma unroll
    for (int i = 0; i < 4; i++){
        int gm = row0 + ty*4 + i;
        if (gm >= M) continue;
        #pragma unroll
        for (int j = 0; j < 4; j++){
            int gn = col0 + tx*4 + j;
            if (gn >= N) continue;
            float v = acc[i][j]*scale;
            if (bias) v += bias[gn];
            if (ACT == 1) v = fmaxf(v, 0.f);
            if (ACT == 2) v = v > 0.f ? v : 0.2f*v;
            C[gm*N + gn] = v;
        }
    }
}

// ---------------- merged Q/K projection: z picks weight set (M=3200,N=128,Kd=128) ----------------
__global__ void __launch_bounds__(256) k_gemmQK(
        const float* __restrict__ A,
        const float* __restrict__ qw, const float* __restrict__ qb,
        const float* __restrict__ kw, const float* __restrict__ kb,
        float* __restrict__ Qo, float* __restrict__ Ko){
    const float* B    = blockIdx.z ? kw : qw;
    const float* bias = blockIdx.z ? kb : qb;
    float*       C    = blockIdx.z ? Ko : Qo;
    __shared__ float As[16][68];
    __shared__ float Bs[16][68];
    int tid = threadIdx.x;
    int tx = tid & 15, ty = tid >> 4;
    int row0 = blockIdx.y*64, col0 = blockIdx.x*64;
    float acc[4][4] = {};
    for (int k0 = 0; k0 < 128; k0 += 16){
        #pragma unroll
        for (int l = 0; l < 4; l++){
            int idx = tid + l*256;
            int m = idx >> 4, k = idx & 15;
            As[k][m] = A[(row0 + m)*128 + k0 + k];
            Bs[k][m] = B[(col0 + m)*128 + k0 + k];
        }
        __syncthreads();
        #pragma unroll
        for (int k = 0; k < 16; k++){
            float4 av = *reinterpret_cast<const float4*>(&As[k][ty*4]);
            float4 bv = *reinterpret_cast<const float4*>(&Bs[k][tx*4]);
            float a[4] = {av.x, av.y, av.z, av.w};
            float bb[4] = {bv.x, bv.y, bv.z, bv.w};
            #pragma unroll
            for (int i = 0; i < 4; i++)
                #pragma unroll
                for (int j = 0; j < 4; j++)
                    acc[i][j] += a[i]*bb[j];
        }
        __syncthreads();
    }
    #pragma unroll
    for (int i = 0; i < 4; i++){
        int gm = row0 + ty*4 + i;
        #pragma unroll
        for (int j = 0; j < 4; j++){
            int gn = col0 + tx*4 + j;
            C[gm*128 + gn] = acc[i][j] + bias[gn];
        }
    }
}

// ---------------- top-K(20) mask + softmax per (t,r) row ----------------
__global__ void k_adj(){
    __shared__ float sa[200];
    __shared__ float red[256];
    int b = blockIdx.x, tid = threadIdx.x;
    int t = b / 200, r = b % 200;
    const float* row = &d_attn[(t*200 + r)*200];
    if (tid < 200) sa[tid] = row[tid];
    __syncthreads();
    float v = NEG9;
    if (tid < 200){
        float my = sa[tid];
        int cnt = 0;
        for (int j = 0; j < 200; j++){
            float aj = sa[j];
            cnt += (aj > my) || (aj == my && j < tid);
        }
        if (cnt < 20) v = (my == 0.f) ? NEG9 : my;
    }
    red[tid] = (tid < 200) ? v : NEG9;
    __syncthreads();
    for (int off = 128; off; off >>= 1){
        if (tid < off) red[tid] = fmaxf(red[tid], red[tid + off]);
        __syncthreads();
    }
    float m = red[0];
    __syncthreads();
    float e = (tid < 200) ? expf(v - m) : 0.f;
    red[tid] = e;
    __syncthreads();
    for (int off = 128; off; off >>= 1){
        if (tid < off) red[tid] += red[tid + off];
        __syncthreads();
    }
    float s = red[0];
    if (tid < 200) d_adj[(t*200 + r)*200 + tid] = e / s;
}

// ---------------- degree + dinv ----------------
__global__ void k_deg(){
    int t = blockIdx.x, s = threadIdx.x;
    if (s >= 200) return;
    const float* a = &d_adj[t*40000];
    float col = 0.f;
    for (int r = 0; r < 200; r++) col += a[r*200 + s];
    float diag = a[s*200 + s];
    float dsl = (diag == 0.f) ? 1.f : diag;
    float deg = col - diag + dsl;
    deg = (deg > 0.f) ? deg : 1.f;
    d_dinv[t*200 + s] = rsqrtf(deg);
}

// ---------------- An[t,r,s] = dinv[r]*adj_sl[t,s,r]*dinv[s] ----------------
__global__ void k_An(){
    int idx = blockIdx.x*256 + threadIdx.x;
    if (idx >= 640000) return;
    int s = idx % 200, r = (idx/200) % 200, t = idx/40000;
    const float* a = &d_adj[t*40000];
    float val;
    if (r == s){
        float diag = a[r*200 + r];
        val = (diag == 0.f) ? 1.f : diag;
    } else {
        val = a[s*200 + r];
    }
    d_An[idx] = d_dinv[t*200 + r] * val * d_dinv[t*200 + s];
}

// ---------------- g_emb = mean over r ----------------
__global__ void k_gemb(){
    int t = blockIdx.x, h = threadIdx.x;
    float s = 0.f;
    #pragma unroll 4
    for (int r = 0; r < 200; r++) s += d_G2[(t*200 + r)*256 + h];
    d_gemb[t*256 + h] = s * (1.f/200.f);
}

// ---------------- GRU ----------------
__global__ void k_gru(const float* __restrict__ whh, const float* __restrict__ bhh,
                      const float* __restrict__ clsw, const float* __restrict__ clsb,
                      float* out){
    __shared__ float hs[256];
    int i = threadIdx.x;
    hs[i] = 0.f;
    __syncthreads();
    float b0 = bhh[i], b1 = bhh[256+i], b2 = bhh[512+i];
    const float4* w0 = (const float4*)(whh + i*256);
    const float4* w1 = (const float4*)(whh + (256+i)*256);
    const float4* w2 = (const float4*)(whh + (512+i)*256);
    for (int t = 0; t < 16; t++){
        const float4* hv = (const float4*)hs;
        float hr = b0, hz = b1, hn = b2;
        #pragma unroll 8
        for (int k = 0; k < 64; k++){
            float4 h4 = hv[k];
            float4 a = __ldg(&w0[k]);
            float4 b = __ldg(&w1[k]);
            float4 c = __ldg(&w2[k]);
            hr += a.x*h4.x + a.y*h4.y + a.z*h4.z + a.w*h4.w;
            hz += b.x*h4.x + b.y*h4.y + b.z*h4.z + b.w*h4.w;
            hn += c.x*h4.x + c.y*h4.y + c.z*h4.z + c.w*h4.w;
        }
        float gir = d_gi[t*768 + i], giz = d_gi[t*768 + 256 + i], gin = d_gi[t*768 + 512 + i];
        float rr = 1.f / (1.f + expf(-(gir + hr)));
        float z  = 1.f / (1.f + expf(-(giz + hz)));
        float nn = tanhf(gin + rr*hn);
        float hnew = (1.f - z)*nn + z*hs[i];
        __syncthreads();
        hs[i] = hnew;
        __syncthreads();
    }
    if (i < 2){
        float s = clsb[i];
        for (int k = 0; k < 256; k++) s += clsw[i*256 + k]*hs[k];
        out[i] = s;
    }
}

// ---------------- avg_adj + edge variance ----------------
__global__ void k_avgvar(float* out){
    __shared__ float red[256];
    int idx = blockIdx.x*256 + threadIdx.x;
    float var = 0.f;
    if (idx < 40000){
        float x[16];
        float s = 0.f;
        #pragma unroll
        for (int t = 0; t < 16; t++){ x[t] = d_adj[t*40000 + idx]; s += x[t]; }
        float mu = s * (1.f/16.f);
        float ssd = 0.f;
        #pragma unroll
        for (int t = 0; t < 16; t++){ float d = x[t] - mu; ssd += d*d; }
        var = ssd * (1.f/15.f);
        out[2 + idx] = mu;
    }
    red[threadIdx.x] = var;
    __syncthreads();
    for (int off = 128; off; off >>= 1){
        if (threadIdx.x < off) red[threadIdx.x] += red[threadIdx.x + off];
        __syncthreads();
    }
    if (threadIdx.x == 0) atomicAdd(&out[40002], red[0] * (1.f/40000.f));
}

// ---------------- driver ----------------
extern "C" void kernel_launch(void* const* d_in, const int* in_sizes, int n_in,
                              void* d_out, int out_size){
    const float* tw   = (const float*)d_in[0];
    const float* wavr = (const float*)d_in[1];
    const float* wavi = (const float*)d_in[2];
    const float* c1w  = (const float*)d_in[3];
    const float* c1b  = (const float*)d_in[4];
    const float* bn1g = (const float*)d_in[5];
    const float* bn1b = (const float*)d_in[6];
    const float* c2w  = (const float*)d_in[7];
    const float* c2b  = (const float*)d_in[8];
    const float* bn2g = (const float*)d_in[9];
    const float* bn2b = (const float*)d_in[10];
    const float* fcw  = (const float*)d_in[11];
    const float* fcb  = (const float*)d_in[12];
    const float* qw   = (const float*)d_in[13];
    const float* qb   = (const float*)d_in[14];
    const float* kw   = (const float*)d_in[15];
    const float* kb   = (const float*)d_in[16];
    const float* g1w  = (const float*)d_in[17];
    const float* g1b  = (const float*)d_in[18];
    const float* g2w  = (const float*)d_in[19];
    const float* g2b  = (const float*)d_in[20];
    const float* wih  = (const float*)d_in[21];
    const float* whh  = (const float*)d_in[22];
    const float* bih  = (const float*)d_in[23];
    const float* bhh  = (const float*)d_in[24];
    const float* clsw = (const float*)d_in[25];
    const float* clsb = (const float*)d_in[26];
    float* out = (float*)d_out;

    float *p_emb, *p_Q, *p_K, *p_attn, *p_An, *p_X1, *p_G1, *p_X2, *p_G2, *p_feat, *p_gemb, *p_gi;
    cudaGetSymbolAddress((void**)&p_emb,  d_emb);
    cudaGetSymbolAddress((void**)&p_Q,    d_Qm);
    cudaGetSymbolAddress((void**)&p_K,    d_Km);
    cudaGetSymbolAddress((void**)&p_attn, d_attn);
    cudaGetSymbolAddress((void**)&p_An,   d_An);
    cudaGetSymbolAddress((void**)&p_X1,   d_X1);
    cudaGetSymbolAddress((void**)&p_G1,   d_G1);
    cudaGetSymbolAddress((void**)&p_X2,   d_X2);
    cudaGetSymbolAddress((void**)&p_G2,   d_G2);
    cudaGetSymbolAddress((void**)&p_feat, d_feat);
    cudaGetSymbolAddress((void**)&p_gemb, d_gemb);
    cudaGetSymbolAddress((void**)&p_gi,   d_gi);

    k_init<<<1, 128>>>(out);
    k_cwtconv1<<<NWIN, 256>>>(tw, wavr, wavi, c1w, c1b);
    k_bn1fin<<<1, 16>>>(bn1g, bn1b);
    k_conv2<<<NWIN, 512>>>(c2w, c2b);
    k_bn2fin<<<1, 32>>>(bn2g, bn2b);
    k_feat<<<NWIN, 256>>>();

    k_gemm<0, true><<<dim3(2, 50, 1), 256>>>(p_feat, fcw, fcb, p_emb, 3200, 128, 32, 0, 0, 0, 1.f);
    k_gemmQK<<<dim3(2, 50, 2), 256>>>(p_emb, qw, qb, kw, kb, p_Q, p_K);
    k_gemm<2, true><<<dim3(4, 4, 16), 256>>>(p_Q, p_K, nullptr, p_attn,
                                             200, 200, 128, 25600, 25600, 40000, 0.08838834764831845f);
    k_adj<<<3200, 256>>>();
    k_deg<<<16, 256>>>();
    k_An<<<2500, 256>>>();
    k_gemm<0, false><<<dim3(4, 50, 1), 256>>>(p_emb, g1w, nullptr, p_X1, 3200, 256, 128, 0, 0, 0, 1.f);
    k_gemm<1, false><<<dim3(4, 4, 16), 256>>>(p_An, p_X1, g1b, p_G1, 200, 256, 200, 40000, 51200, 51200, 1.f);
    k_gemm<0, false><<<dim3(4, 50, 1), 256>>>(p_G1, g2w, nullptr, p_X2, 3200, 256, 256, 0, 0, 0, 1.f);
    k_gemm<1, false><<<dim3(4, 4, 16), 256>>>(p_An, p_X2, g2b, p_G2, 200, 256, 200, 40000, 51200, 51200, 1.f);
    k_gemb<<<16, 256>>>();
    k_gemm<0, true><<<dim3(12, 1, 1), 256>>>(p_gemb, wih, bih, p_gi, 16, 768, 256, 0, 0, 0, 1.f);
    k_gru<<<1, 256>>>(whh, bhh, clsw, clsb, out);
    k_avgvar<<<157, 256>>>(out);
}

// round 6
// speedup vs baseline: 1.0408x; 1.0408x over previous
#include <cuda_runtime.h>
#include <math.h>

#define NWIN 3200
#define NEG9 -1000000000.0f

// ---------------- static scratch ----------------
__device__ float  d_c1max[NWIN*16*16*32];   // (n,ci,y,32) x-padded, x<25 valid
__device__ float  d_c1min[NWIN*16*16*32];
__device__ float  d_c2max[NWIN*32*8*12];
__device__ float  d_c2min[NWIN*32*8*12];
__device__ float  d_feat[NWIN*32];
__device__ float  d_emb [NWIN*128];
__device__ float  d_Qm  [NWIN*128];
__device__ float  d_Km  [NWIN*128];
__device__ float  d_attn[16*200*200];
__device__ float  d_adj [16*200*200];
__device__ float  d_dinv[16*200];
__device__ float  d_An  [16*200*200];
__device__ float  d_X1  [NWIN*256];
__device__ float  d_G1  [NWIN*256];
__device__ float  d_X2  [NWIN*256];
__device__ float  d_G2  [NWIN*256];
__device__ float  d_gemb[16*256];
__device__ float  d_gi  [16*768];
__device__ double d_bnsum[96];
__device__ float  d_sc1[16], d_sh1[16];   // kept for layout compat (unused now)

__global__ void k_init(float* out){
    int t = threadIdx.x;
    if (t < 96) d_bnsum[t] = 0.0;
    if (t == 96) out[40002] = 0.f;
}

// ---------------- fused CWT + conv1(1->16) + BN stats + raw 2x2 max/min pool ----------------
__global__ void __launch_bounds__(256) k_cwtconv1(
        const float* __restrict__ x, const float* __restrict__ wr,
        const float* __restrict__ wi, const float* __restrict__ w,
        const float* __restrict__ b){
    __shared__ float xp[112];
    __shared__ float wrs[1600], wis[1600];
    __shared__ float sp[34*52];
    __shared__ float ssum[16], ssq[16];
    int n = blockIdx.x, tid = threadIdx.x;
    if (tid < 16){ ssum[tid] = 0.f; ssq[tid] = 0.f; }
    for (int i = tid; i < 112; i += 256){
        int s = i - 24;
        xp[i] = (s >= 0 && s < 50) ? x[n*50 + s] : 0.f;
    }
    for (int i = tid; i < 1600; i += 256){ wrs[i] = wr[i]; wis[i] = wi[i]; }
    for (int i = tid; i < 34*52; i += 256) sp[i] = 0.f;
    __syncthreads();

    // ---- CWT: 7 consecutive outputs per thread ----
    {
        int f = tid >> 3, jb = (tid & 7) * 7;
        const float* a  = &wrs[f*50];
        const float* bb = &wis[f*50];
        float re[7] = {0,0,0,0,0,0,0}, im[7] = {0,0,0,0,0,0,0};
        float win[7];
        #pragma unroll
        for (int q = 0; q < 7; q++) win[q] = xp[jb + q];
        #pragma unroll
        for (int k = 0; k < 50; k++){
            float wa = a[k], wb = bb[k];
            #pragma unroll
            for (int q = 0; q < 7; q++){ re[q] += win[q]*wa; im[q] += win[q]*wb; }
            #pragma unroll
            for (int q = 0; q < 6; q++) win[q] = win[q+1];
            win[6] = xp[jb + k + 7];
        }
        #pragma unroll
        for (int q = 0; q < 7; q++){
            int j = jb + q;
            if (j < 50) sp[(f+1)*52 + (j+1)] = sqrtf(re[q]*re[q] + im[q]*im[q]);
        }
    }
    __syncthreads();

    // ---- conv1: thread = (c, ypair); 2 output rows, sliding 4-row window ----
    int c = tid >> 4, yp = tid & 15;
    float wl[9];
    #pragma unroll
    for (int k = 0; k < 9; k++) wl[k] = __ldg(&w[c*9 + k]);
    float bias = __ldg(&b[c]);
    const float* r0 = &sp[(2*yp + 0)*52];
    const float* r1 = &sp[(2*yp + 1)*52];
    const float* r2 = &sp[(2*yp + 2)*52];
    const float* r3 = &sp[(2*yp + 3)*52];
    float a0=r0[0], b0=r0[1], a1=r1[0], b1=r1[1];
    float a2=r2[0], b2=r2[1], a3=r3[0], b3=r3[1];
    float s = 0.f, sq = 0.f, pm = 0.f, pn = 0.f;
    float* omax = &d_c1max[((n*16 + c)*16 + yp)*32];
    float* omin = &d_c1min[((n*16 + c)*16 + yp)*32];
    #pragma unroll
    for (int xx = 0; xx < 50; xx++){
        float c0=r0[xx+2], c1=r1[xx+2], c2=r2[xx+2], c3=r3[xx+2];
        float o0 = bias + a0*wl[0]+b0*wl[1]+c0*wl[2]
                        + a1*wl[3]+b1*wl[4]+c1*wl[5]
                        + a2*wl[6]+b2*wl[7]+c2*wl[8];
        float o1 = bias + a1*wl[0]+b1*wl[1]+c1*wl[2]
                        + a2*wl[3]+b2*wl[4]+c2*wl[5]
                        + a3*wl[6]+b3*wl[7]+c3*wl[8];
        s += o0 + o1; sq += o0*o0 + o1*o1;
        float mx = fmaxf(o0,o1), mn = fminf(o0,o1);
        if ((xx & 1) == 0){ pm = mx; pn = mn; }
        else { omax[xx>>1] = fmaxf(pm, mx); omin[xx>>1] = fminf(pn, mn); }
        a0=b0; b0=c0; a1=b1; b1=c1; a2=b2; b2=c2; a3=b3; b3=c3;
    }
    atomicAdd(&ssum[c], s); atomicAdd(&ssq[c], sq);
    __syncthreads();
    if (tid < 16){
        atomicAdd(&d_bnsum[tid],      (double)ssum[tid]);
        atomicAdd(&d_bnsum[16 + tid], (double)ssq[tid]);
    }
}

// ---------------- conv2 (16->32): 256 thr, 2 rows/thread, float2 LDS, fused BN1 ----------------
__global__ void __launch_bounds__(256) k_conv2(const float* __restrict__ w,
                                               const float* __restrict__ b,
                                               const float* __restrict__ g1,
                                               const float* __restrict__ b1){
    __shared__ float sp[16*504];     // 16 x 18 x 28 (rows padded to 28 -> 8B-aligned pairs)
    __shared__ float ssum[32], ssq[32];
    __shared__ float ssc[16], ssh[16];
    int n = blockIdx.x, tid = threadIdx.x;
    if (tid < 32){ ssum[tid] = 0.f; ssq[tid] = 0.f; }
    if (tid < 16){
        double cnt = 5120000.0;
        double mu  = d_bnsum[tid] / cnt;
        double var = d_bnsum[16 + tid] / cnt - mu*mu;
        float sc = g1[tid] * rsqrtf((float)var + 1e-5f);
        ssc[tid] = sc;
        ssh[tid] = b1[tid] - (float)mu * sc;
    }
    for (int i = tid; i < 16*504; i += 256) sp[i] = 0.f;
    __syncthreads();
    // load pooled conv1 (x-stride-32 layout) + apply BN1+relu via max/min select
    for (int i = tid; i < 8192; i += 256){
        int xx = i & 31;
        if (xx < 25){
            int y = (i >> 5) & 15, ci = i >> 9;
            float sc = ssc[ci], sh = ssh[ci];
            float mx = d_c1max[n*8192 + i], mn = d_c1min[n*8192 + i];
            float v = fmaxf(sc * (sc >= 0.f ? mx : mn) + sh, 0.f);
            sp[ci*504 + (y+1)*28 + (xx+1)] = v;
        }
    }
    __syncthreads();

    int c = tid >> 3, yp = tid & 7;           // c in 0..31, yp in 0..7 (row pair)
    float bias = __ldg(&b[c]);
    float acc0[25], acc1[25];
    #pragma unroll
    for (int k = 0; k < 25; k++){ acc0[k] = bias; acc1[k] = bias; }
    for (int ci = 0; ci < 16; ci++){
        const float* wp = &w[(c*16 + ci)*9];
        float w0=__ldg(wp+0),w1=__ldg(wp+1),w2=__ldg(wp+2),
              w3=__ldg(wp+3),w4=__ldg(wp+4),w5=__ldg(wp+5),
              w6=__ldg(wp+6),w7=__ldg(wp+7),w8=__ldg(wp+8);
        const float* r0 = &sp[ci*504 + (2*yp + 0)*28];
        const float* r1 = &sp[ci*504 + (2*yp + 1)*28];
        const float* r2 = &sp[ci*504 + (2*yp + 2)*28];
        const float* r3 = &sp[ci*504 + (2*yp + 3)*28];
        float a0=r0[0], b0=r0[1], a1=r1[0], b1=r1[1];
        float a2=r2[0], b2=r2[1], a3=r3[0], b3=r3[1];
        #pragma unroll
        for (int m = 0; m < 12; m++){
            float2 c0 = *reinterpret_cast<const float2*>(&r0[2*m+2]);
            float2 c1 = *reinterpret_cast<const float2*>(&r1[2*m+2]);
            float2 c2 = *reinterpret_cast<const float2*>(&r2[2*m+2]);
            float2 c3 = *reinterpret_cast<const float2*>(&r3[2*m+2]);
            acc0[2*m]   += a0*w0 + b0*w1 + c0.x*w2
                         + a1*w3 + b1*w4 + c1.x*w5
                         + a2*w6 + b2*w7 + c2.x*w8;
            acc0[2*m+1] += b0*w0 + c0.x*w1 + c0.y*w2
                         + b1*w3 + c1.x*w4 + c1.y*w5
                         + b2*w6 + c2.x*w7 + c2.y*w8;
            acc1[2*m]   += a1*w0 + b1*w1 + c1.x*w2
                         + a2*w3 + b2*w4 + c2.x*w5
                         + a3*w6 + b3*w7 + c3.x*w8;
            acc1[2*m+1] += b1*w0 + c1.x*w1 + c1.y*w2
                         + b2*w3 + c2.x*w4 + c2.y*w5
                         + b3*w6 + c3.x*w7 + c3.y*w8;
            a0=c0.x; b0=c0.y; a1=c1.x; b1=c1.y;
            a2=c2.x; b2=c2.y; a3=c3.x; b3=c3.y;
        }
        float e0=r0[26], e1=r1[26], e2=r2[26], e3=r3[26];
        acc0[24] += a0*w0 + b0*w1 + e0*w2
                  + a1*w3 + b1*w4 + e1*w5
                  + a2*w6 + b2*w7 + e2*w8;
        acc1[24] += a1*w0 + b1*w1 + e1*w2
                  + a2*w3 + b2*w4 + e2*w5
                  + a3*w6 + b3*w7 + e3*w8;
    }
    float s = 0.f, sq = 0.f;
    #pragma unroll
    for (int k = 0; k < 25; k++){
        s  += acc0[k] + acc1[k];
        sq += acc0[k]*acc0[k] + acc1[k]*acc1[k];
    }
    atomicAdd(&ssum[c], s); atomicAdd(&ssq[c], sq);
    float* omax = &d_c2max[((n*32 + c)*8 + yp)*12];
    float* omin = &d_c2min[((n*32 + c)*8 + yp)*12];
    #pragma unroll
    for (int xq = 0; xq < 12; xq++){
        float m0 = fmaxf(acc0[2*xq], acc0[2*xq+1]);
        float m1 = fmaxf(acc1[2*xq], acc1[2*xq+1]);
        omax[xq] = fmaxf(m0, m1);
        float n0 = fminf(acc0[2*xq], acc0[2*xq+1]);
        float n1 = fminf(acc1[2*xq], acc1[2*xq+1]);
        omin[xq] = fminf(n0, n1);
    }
    __syncthreads();
    if (tid < 32){
        atomicAdd(&d_bnsum[32 + tid], (double)ssum[tid]);
        atomicAdd(&d_bnsum[64 + tid], (double)ssq[tid]);
    }
}

// ---------------- feat: fused BN2 + relu on pooled, spatial mean -> (n,32) ----------------
__global__ void k_feat(const float* __restrict__ g2, const float* __restrict__ b2){
    __shared__ float red[256];
    __shared__ float ssc[32], ssh[32];
    int n = blockIdx.x, tid = threadIdx.x;
    if (tid < 32){
        double cnt = 1280000.0;
        double mu  = d_bnsum[32 + tid] / cnt;
        double var = d_bnsum[64 + tid] / cnt - mu*mu;
        float sc = g2[tid] * rsqrtf((float)var + 1e-5f);
        ssc[tid] = sc;
        ssh[tid] = b2[tid] - (float)mu * sc;
    }
    __syncthreads();
    int c = tid & 31, yp = tid >> 5;
    float sc = ssc[c], sh = ssh[c];
    const float* pmax = &d_c2max[((n*32 + c)*8 + yp)*12];
    const float* pmin = &d_c2min[((n*32 + c)*8 + yp)*12];
    float s = 0.f;
    #pragma unroll
    for (int xq = 0; xq < 12; xq++){
        float v = sc >= 0.f ? pmax[xq] : pmin[xq];
        s += fmaxf(sc*v + sh, 0.f);
    }
    red[tid] = s;
    __syncthreads();
    if (tid < 32){
        float t = 0.f;
        #pragma unroll
        for (int q = 0; q < 8; q++) t += red[q*32 + tid];
        d_feat[n*32 + tid] = t * (1.f/96.f);
    }
}

// ---------------- generic tiled SGEMM (64x64x16, 4x4 micro) ----------------
template<int ACT, bool TRANSB>
__global__ void __launch_bounds__(256) k_gemm(
        const float* __restrict__ A, const float* __restrict__ B,
        const float* __restrict__ bias, float* __restrict__ C,
        int M, int N, int Kd, int sA, int sB, int sC, float scale){
    __shared__ float As[16][68];
    __shared__ float Bs[16][68];
    int bz = blockIdx.z;
    A += (long)bz*sA; B += (long)bz*sB; C += (long)bz*sC;
    int tid = threadIdx.x;
    int tx = tid & 15, ty = tid >> 4;
    int row0 = blockIdx.y*64, col0 = blockIdx.x*64;
    float acc[4][4] = {};
    for (int k0 = 0; k0 < Kd; k0 += 16){
        #pragma unroll
        for (int l = 0; l < 4; l++){
            int idx = tid + l*256;
            int m = idx >> 4, k = idx & 15;
            int gm = row0 + m, gk = k0 + k;
            As[k][m] = (gm < M && gk < Kd) ? A[gm*Kd + gk] : 0.f;
        }
        #pragma unroll
        for (int l = 0; l < 4; l++){
            int idx = tid + l*256;
            if (TRANSB){
                int nn = idx >> 4, k = idx & 15;
                int gn = col0 + nn, gk = k0 + k;
                Bs[k][nn] = (gn < N && gk < Kd) ? B[gn*Kd + gk] : 0.f;
            } else {
                int k = idx >> 6, nn = idx & 63;
                int gn = col0 + nn, gk = k0 + k;
                Bs[k][nn] = (gn < N && gk < Kd) ? B[gk*N + gn] : 0.f;
            }
        }
        __syncthreads();
        #pragma unroll
        for (int k = 0; k < 16; k++){
            float4 av = *reinterpret_cast<const float4*>(&As[k][ty*4]);
            float4 bv = *reinterpret_cast<const float4*>(&Bs[k][tx*4]);
            float a[4] = {av.x, av.y, av.z, av.w};
            float bb[4] = {bv.x, bv.y, bv.z, bv.w};
            #pragma unroll
            for (int i = 0; i < 4; i++)
                #pragma unroll
                for (int j = 0; j < 4; j++)
                    acc[i][j] += a[i]*bb[j];
        }
        __syncthreads();
    }
    #pragma unroll
    for (int i = 0; i < 4; i++){
        int gm = row0 + ty*4 + i;
        if (gm >= M) continue;
        #pragma unroll
        for (int j = 0; j < 4; j++){
            int gn = col0 + tx*4 + j;
            if (gn >= N) continue;
            float v = acc[i][j]*scale;
            if (bias) v += bias[gn];
            if (ACT == 1) v = fmaxf(v, 0.f);
            if (ACT == 2) v = v > 0.f ? v : 0.2f*v;
            C[gm*N + gn] = v;
        }
    }
}

// ---------------- merged Q/K projection ----------------
__global__ void __launch_bounds__(256) k_gemmQK(
        const float* __restrict__ A,
        const float* __restrict__ qw, const float* __restrict__ qb,
        const float* __restrict__ kw, const float* __restrict__ kb,
        float* __restrict__ Qo, float* __restrict__ Ko){
    const float* B    = blockIdx.z ? kw : qw;
    const float* bias = blockIdx.z ? kb : qb;
    float*       C    = blockIdx.z ? Ko : Qo;
    __shared__ float As[16][68];
    __shared__ float Bs[16][68];
    int tid = threadIdx.x;
    int tx = tid & 15, ty = tid >> 4;
    int row0 = blockIdx.y*64, col0 = blockIdx.x*64;
    float acc[4][4] = {};
    for (int k0 = 0; k0 < 128; k0 += 16){
        #pragma unroll
        for (int l = 0; l < 4; l++){
            int idx = tid + l*256;
            int m = idx >> 4, k = idx & 15;
            As[k][m] = A[(row0 + m)*128 + k0 + k];
            Bs[k][m] = B[(col0 + m)*128 + k0 + k];
        }
        __syncthreads();
        #pragma unroll
        for (int k = 0; k < 16; k++){
            float4 av = *reinterpret_cast<const float4*>(&As[k][ty*4]);
            float4 bv = *reinterpret_cast<const float4*>(&Bs[k][tx*4]);
            float a[4] = {av.x, av.y, av.z, av.w};
            float bb[4] = {bv.x, bv.y, bv.z, bv.w};
            #pragma unroll
            for (int i = 0; i < 4; i++)
                #pragma unroll
                for (int j = 0; j < 4; j++)
                    acc[i][j] += a[i]*bb[j];
        }
        __syncthreads();
    }
    #pragma unroll
    for (int i = 0; i < 4; i++){
        int gm = row0 + ty*4 + i;
        #pragma unroll
        for (int j = 0; j < 4; j++){
            int gn = col0 + tx*4 + j;
            C[gm*128 + gn] = acc[i][j] + bias[gn];
        }
    }
}

// ---------------- top-K(20) mask + softmax per (t,r) row ----------------
__global__ void k_adj(){
    __shared__ float sa[200];
    __shared__ float red[256];
    int b = blockIdx.x, tid = threadIdx.x;
    int t = b / 200, r = b % 200;
    const float* row = &d_attn[(t*200 + r)*200];
    if (tid < 200) sa[tid] = row[tid];
    __syncthreads();
    float v = NEG9;
    if (tid < 200){
        float my = sa[tid];
        int cnt = 0;
        for (int j = 0; j < 200; j++){
            float aj = sa[j];
            cnt += (aj > my) || (aj == my && j < tid);
        }
        if (cnt < 20) v = (my == 0.f) ? NEG9 : my;
    }
    red[tid] = (tid < 200) ? v : NEG9;
    __syncthreads();
    for (int off = 128; off; off >>= 1){
        if (tid < off) red[tid] = fmaxf(red[tid], red[tid + off]);
        __syncthreads();
    }
    float m = red[0];
    __syncthreads();
    float e = (tid < 200) ? expf(v - m) : 0.f;
    red[tid] = e;
    __syncthreads();
    for (int off = 128; off; off >>= 1){
        if (tid < off) red[tid] += red[tid + off];
        __syncthreads();
    }
    float s = red[0];
    if (tid < 200) d_adj[(t*200 + r)*200 + tid] = e / s;
}

// ---------------- degree + dinv ----------------
__global__ void k_deg(){
    int t = blockIdx.x, s = threadIdx.x;
    if (s >= 200) return;
    const float* a = &d_adj[t*40000];
    float col = 0.f;
    for (int r = 0; r < 200; r++) col += a[r*200 + s];
    float diag = a[s*200 + s];
    float dsl = (diag == 0.f) ? 1.f : diag;
    float deg = col - diag + dsl;
    deg = (deg > 0.f) ? deg : 1.f;
    d_dinv[t*200 + s] = rsqrtf(deg);
}

// ---------------- An[t,r,s] = dinv[r]*adj_sl[t,s,r]*dinv[s] ----------------
__global__ void k_An(){
    int idx = blockIdx.x*256 + threadIdx.x;
    if (idx >= 640000) return;
    int s = idx % 200, r = (idx/200) % 200, t = idx/40000;
    const float* a = &d_adj[t*40000];
    float val;
    if (r == s){
        float diag = a[r*200 + r];
        val = (diag == 0.f) ? 1.f : diag;
    } else {
        val = a[s*200 + r];
    }
    d_An[idx] = d_dinv[t*200 + r] * val * d_dinv[t*200 + s];
}

// ---------------- g_emb = mean over r ----------------
__global__ void k_gemb(){
    int t = blockIdx.x, h = threadIdx.x;
    float s = 0.f;
    #pragma unroll 4
    for (int r = 0; r < 200; r++) s += d_G2[(t*200 + r)*256 + h];
    d_gemb[t*256 + h] = s * (1.f/200.f);
}

// ---------------- GRU ----------------
__global__ void k_gru(const float* __restrict__ whh, const float* __restrict__ bhh,
                      const float* __restrict__ clsw, const float* __restrict__ clsb,
                      float* out){
    __shared__ float hs[256];
    int i = threadIdx.x;
    hs[i] = 0.f;
    __syncthreads();
    float b0 = bhh[i], b1 = bhh[256+i], b2 = bhh[512+i];
    const float4* w0 = (const float4*)(whh + i*256);
    const float4* w1 = (const float4*)(whh + (256+i)*256);
    const float4* w2 = (const float4*)(whh + (512+i)*256);
    for (int t = 0; t < 16; t++){
        const float4* hv = (const float4*)hs;
        float hr = b0, hz = b1, hn = b2;
        #pragma unroll 8
        for (int k = 0; k < 64; k++){
            float4 h4 = hv[k];
            float4 a = __ldg(&w0[k]);
            float4 b = __ldg(&w1[k]);
            float4 c = __ldg(&w2[k]);
            hr += a.x*h4.x + a.y*h4.y + a.z*h4.z + a.w*h4.w;
            hz += b.x*h4.x + b.y*h4.y + b.z*h4.z + b.w*h4.w;
            hn += c.x*h4.x + c.y*h4.y + c.z*h4.z + c.w*h4.w;
        }
        float gir = d_gi[t*768 + i], giz = d_gi[t*768 + 256 + i], gin = d_gi[t*768 + 512 + i];
        float rr = 1.f / (1.f + expf(-(gir + hr)));
        float z  = 1.f / (1.f + expf(-(giz + hz)));
        float nn = tanhf(gin + rr*hn);
        float hnew = (1.f - z)*nn + z*hs[i];
        __syncthreads();
        hs[i] = hnew;
        __syncthreads();
    }
    if (i < 2){
        float s = clsb[i];
        for (int k = 0; k < 256; k++) s += clsw[i*256 + k]*hs[k];
        out[i] = s;
    }
}

// ---------------- avg_adj + edge variance ----------------
__global__ void k_avgvar(float* out){
    __shared__ float red[256];
    int idx = blockIdx.x*256 + threadIdx.x;
    float var = 0.f;
    if (idx < 40000){
        float x[16];
        float s = 0.f;
        #pragma unroll
        for (int t = 0; t < 16; t++){ x[t] = d_adj[t*40000 + idx]; s += x[t]; }
        float mu = s * (1.f/16.f);
        float ssd = 0.f;
        #pragma unroll
        for (int t = 0; t < 16; t++){ float d = x[t] - mu; ssd += d*d; }
        var = ssd * (1.f/15.f);
        out[2 + idx] = mu;
    }
    red[threadIdx.x] = var;
    __syncthreads();
    for (int off = 128; off; off >>= 1){
        if (threadIdx.x < off) red[threadIdx.x] += red[threadIdx.x + off];
        __syncthreads();
    }
    if (threadIdx.x == 0) atomicAdd(&out[40002], red[0] * (1.f/40000.f));
}

// ---------------- driver ----------------
extern "C" void kernel_launch(void* const* d_in, const int* in_sizes, int n_in,
                              void* d_out, int out_size){
    const float* tw   = (const float*)d_in[0];
    const float* wavr = (const float*)d_in[1];
    const float* wavi = (const float*)d_in[2];
    const float* c1w  = (const float*)d_in[3];
    const float* c1b  = (const float*)d_in[4];
    const float* bn1g = (const float*)d_in[5];
    const float* bn1b = (const float*)d_in[6];
    const float* c2w  = (const float*)d_in[7];
    const float* c2b  = (const float*)d_in[8];
    const float* bn2g = (const float*)d_in[9];
    const float* bn2b = (const float*)d_in[10];
    const float* fcw  = (const float*)d_in[11];
    const float* fcb  = (const float*)d_in[12];
    const float* qw   = (const float*)d_in[13];
    const float* qb   = (const float*)d_in[14];
    const float* kw   = (const float*)d_in[15];
    const float* kb   = (const float*)d_in[16];
    const float* g1w  = (const float*)d_in[17];
    const float* g1b  = (const float*)d_in[18];
    const float* g2w  = (const float*)d_in[19];
    const float* g2b  = (const float*)d_in[20];
    const float* wih  = (const float*)d_in[21];
    const float* whh  = (const float*)d_in[22];
    const float* bih  = (const float*)d_in[23];
    const float* bhh  = (const float*)d_in[24];
    const float* clsw = (const float*)d_in[25];
    const float* clsb = (const float*)d_in[26];
    float* out = (float*)d_out;

    float *p_emb, *p_Q, *p_K, *p_attn, *p_An, *p_X1, *p_G1, *p_X2, *p_G2, *p_feat, *p_gemb, *p_gi;
    cudaGetSymbolAddress((void**)&p_emb,  d_emb);
    cudaGetSymbolAddress((void**)&p_Q,    d_Qm);
    cudaGetSymbolAddress((void**)&p_K,    d_Km);
    cudaGetSymbolAddress((void**)&p_attn, d_attn);
    cudaGetSymbolAddress((void**)&p_An,   d_An);
    cudaGetSymbolAddress((void**)&p_X1,   d_X1);
    cudaGetSymbolAddress((void**)&p_G1,   d_G1);
    cudaGetSymbolAddress((void**)&p_X2,   d_X2);
    cudaGetSymbolAddress((void**)&p_G2,   d_G2);
    cudaGetSymbolAddress((void**)&p_feat, d_feat);
    cudaGetSymbolAddress((void**)&p_gemb, d_gemb);
    cudaGetSymbolAddress((void**)&p_gi,   d_gi);

    k_init<<<1, 128>>>(out);
    k_cwtconv1<<<NWIN, 256>>>(tw, wavr, wavi, c1w, c1b);
    k_conv2<<<NWIN, 256>>>(c2w, c2b, bn1g, bn1b);
    k_feat<<<NWIN, 256>>>(bn2g, bn2b);

    k_gemm<0, true><<<dim3(2, 50, 1), 256>>>(p_feat, fcw, fcb, p_emb, 3200, 128, 32, 0, 0, 0, 1.f);
    k_gemmQK<<<dim3(2, 50, 2), 256>>>(p_emb, qw, qb, kw, kb, p_Q, p_K);
    k_gemm<2, true><<<dim3(4, 4, 16), 256>>>(p_Q, p_K, nullptr, p_attn,
                                             200, 200, 128, 25600, 25600, 40000, 0.08838834764831845f);
    k_adj<<<3200, 256>>>();
    k_deg<<<16, 256>>>();
    k_An<<<2500, 256>>>();
    k_gemm<0, false><<<dim3(4, 50, 1), 256>>>(p_emb, g1w, nullptr, p_X1, 3200, 256, 128, 0, 0, 0, 1.f);
    k_gemm<1, false><<<dim3(4, 4, 16), 256>>>(p_An, p_X1, g1b, p_G1, 200, 256, 200, 40000, 51200, 51200, 1.f);
    k_gemm<0, false><<<dim3(4, 50, 1), 256>>>(p_G1, g2w, nullptr, p_X2, 3200, 256, 256, 0, 0, 0, 1.f);
    k_gemm<1, false><<<dim3(4, 4, 16), 256>>>(p_An, p_X2, g2b, p_G2, 200, 256, 200, 40000, 51200, 51200, 1.f);
    k_gemb<<<16, 256>>>();
    k_gemm<0, true><<<dim3(12, 1, 1), 256>>>(p_gemb, wih, bih, p_gi, 16, 768, 256, 0, 0, 0, 1.f);
    k_gru<<<1, 256>>>(whh, bhh, clsw, clsb, out);
    k_avgvar<<<157, 256>>>(out);
}

// round 7
// speedup vs baseline: 1.2032x; 1.1561x over previous
#include <cuda_runtime.h>
#include <math.h>

#define NWIN 3200
#define NEG9 -1000000000.0f

// ---------------- static scratch ----------------
__device__ float  d_c1max[NWIN*16*16*32];   // (n,ci,y,32) x-padded, x<25 valid
__device__ float  d_c1min[NWIN*16*16*32];
__device__ float  d_c2max[NWIN*32*8*16];    // (n,c,yp,16) x-padded, xq<12 valid
__device__ float  d_c2min[NWIN*32*8*16];
__device__ float  d_feat[NWIN*32];
__device__ float  d_emb [NWIN*128];
__device__ float  d_Qm  [NWIN*128];
__device__ float  d_Km  [NWIN*128];
__device__ float  d_attn[16*200*200];
__device__ float  d_adj [16*200*200];
__device__ float  d_dinv[16*200];
__device__ float  d_An  [16*200*200];
__device__ float  d_X1  [NWIN*256];
__device__ float  d_G1  [NWIN*256];
__device__ float  d_X2  [NWIN*256];
__device__ float  d_G2  [NWIN*256];
__device__ float  d_gemb[16*256];
__device__ float  d_gi  [16*768];
__device__ double d_bnsum[96];

__global__ void k_init(float* out){
    int t = threadIdx.x;
    if (t < 96) d_bnsum[t] = 0.0;
    if (t == 96) out[40002] = 0.f;
}

__global__ void k_noop(){}

// ---------------- fused CWT + conv1(1->16) + BN stats + raw 2x2 max/min pool ----------------
__global__ void __launch_bounds__(256) k_cwtconv1(
        const float* __restrict__ x, const float* __restrict__ wr,
        const float* __restrict__ wi, const float* __restrict__ w,
        const float* __restrict__ b){
    __shared__ float xp[112];
    __shared__ float wrs[1600], wis[1600];
    __shared__ float sp[34*52];
    __shared__ float ssum[16], ssq[16];
    int n = blockIdx.x, tid = threadIdx.x;
    if (tid < 16){ ssum[tid] = 0.f; ssq[tid] = 0.f; }
    for (int i = tid; i < 112; i += 256){
        int s = i - 24;
        xp[i] = (s >= 0 && s < 50) ? x[n*50 + s] : 0.f;
    }
    for (int i = tid; i < 1600; i += 256){ wrs[i] = wr[i]; wis[i] = wi[i]; }
    for (int i = tid; i < 34*52; i += 256) sp[i] = 0.f;
    __syncthreads();

    // ---- CWT: 7 consecutive outputs per thread ----
    {
        int f = tid >> 3, jb = (tid & 7) * 7;
        const float* a  = &wrs[f*50];
        const float* bb = &wis[f*50];
        float re[7] = {0,0,0,0,0,0,0}, im[7] = {0,0,0,0,0,0,0};
        float win[7];
        #pragma unroll
        for (int q = 0; q < 7; q++) win[q] = xp[jb + q];
        #pragma unroll
        for (int k = 0; k < 50; k++){
            float wa = a[k], wb = bb[k];
            #pragma unroll
            for (int q = 0; q < 7; q++){ re[q] += win[q]*wa; im[q] += win[q]*wb; }
            #pragma unroll
            for (int q = 0; q < 6; q++) win[q] = win[q+1];
            win[6] = xp[jb + k + 7];
        }
        #pragma unroll
        for (int q = 0; q < 7; q++){
            int j = jb + q;
            if (j < 50) sp[(f+1)*52 + (j+1)] = sqrtf(re[q]*re[q] + im[q]*im[q]);
        }
    }
    __syncthreads();

    // ---- conv1: thread = (c, ypair); 2 output rows, sliding 4-row window ----
    int c = tid >> 4, yp = tid & 15;
    float wl[9];
    #pragma unroll
    for (int k = 0; k < 9; k++) wl[k] = __ldg(&w[c*9 + k]);
    float bias = __ldg(&b[c]);
    const float* r0 = &sp[(2*yp + 0)*52];
    const float* r1 = &sp[(2*yp + 1)*52];
    const float* r2 = &sp[(2*yp + 2)*52];
    const float* r3 = &sp[(2*yp + 3)*52];
    float a0=r0[0], b0=r0[1], a1=r1[0], b1=r1[1];
    float a2=r2[0], b2=r2[1], a3=r3[0], b3=r3[1];
    float s = 0.f, sq = 0.f, pm = 0.f, pn = 0.f;
    float* omax = &d_c1max[((n*16 + c)*16 + yp)*32];
    float* omin = &d_c1min[((n*16 + c)*16 + yp)*32];
    #pragma unroll
    for (int xx = 0; xx < 50; xx++){
        float c0=r0[xx+2], c1=r1[xx+2], c2=r2[xx+2], c3=r3[xx+2];
        float o0 = bias + a0*wl[0]+b0*wl[1]+c0*wl[2]
                        + a1*wl[3]+b1*wl[4]+c1*wl[5]
                        + a2*wl[6]+b2*wl[7]+c2*wl[8];
        float o1 = bias + a1*wl[0]+b1*wl[1]+c1*wl[2]
                        + a2*wl[3]+b2*wl[4]+c2*wl[5]
                        + a3*wl[6]+b3*wl[7]+c3*wl[8];
        s += o0 + o1; sq += o0*o0 + o1*o1;
        float mx = fmaxf(o0,o1), mn = fminf(o0,o1);
        if ((xx & 1) == 0){ pm = mx; pn = mn; }
        else { omax[xx>>1] = fmaxf(pm, mx); omin[xx>>1] = fminf(pn, mn); }
        a0=b0; b0=c0; a1=b1; b1=c1; a2=b2; b2=c2; a3=b3; b3=c3;
    }
    atomicAdd(&ssum[c], s); atomicAdd(&ssq[c], sq);
    __syncthreads();
    if (tid < 16){
        atomicAdd(&d_bnsum[tid],      (double)ssum[tid]);
        atomicAdd(&d_bnsum[16 + tid], (double)ssq[tid]);
    }
}

// ---------------- conv2 (16->32): R4 scalar formulation + fused BN1 ----------------
__global__ void __launch_bounds__(256) k_conv2(const float* __restrict__ w,
                                               const float* __restrict__ b,
                                               const float* __restrict__ g1,
                                               const float* __restrict__ b1){
    __shared__ float sp[16*504];     // 16 x 18 x 28
    __shared__ float ssum[32], ssq[32];
    __shared__ float ssc[16], ssh[16];
    int n = blockIdx.x, tid = threadIdx.x;
    if (tid < 32){ ssum[tid] = 0.f; ssq[tid] = 0.f; }
    if (tid < 16){
        double cnt = 5120000.0;
        double mu  = d_bnsum[tid] / cnt;
        double var = d_bnsum[16 + tid] / cnt - mu*mu;
        float sc = g1[tid] * rsqrtf((float)var + 1e-5f);
        ssc[tid] = sc;
        ssh[tid] = b1[tid] - (float)mu * sc;
    }
    for (int i = tid; i < 16*504; i += 256) sp[i] = 0.f;
    __syncthreads();
    for (int i = tid; i < 8192; i += 256){
        int xx = i & 31;
        if (xx < 25){
            int y = (i >> 5) & 15, ci = i >> 9;
            float sc = ssc[ci], sh = ssh[ci];
            float mx = d_c1max[n*8192 + i], mn = d_c1min[n*8192 + i];
            float v = fmaxf(sc * (sc >= 0.f ? mx : mn) + sh, 0.f);
            sp[ci*504 + (y+1)*28 + (xx+1)] = v;
        }
    }
    __syncthreads();

    int c = tid >> 3, yp = tid & 7;
    float bias = __ldg(&b[c]);
    float acc0[25], acc1[25];
    #pragma unroll
    for (int xx = 0; xx < 25; xx++){ acc0[xx] = bias; acc1[xx] = bias; }
    for (int ci = 0; ci < 16; ci++){
        const float* wp = &w[(c*16 + ci)*9];
        float w0=__ldg(wp+0),w1=__ldg(wp+1),w2=__ldg(wp+2),
              w3=__ldg(wp+3),w4=__ldg(wp+4),w5=__ldg(wp+5),
              w6=__ldg(wp+6),w7=__ldg(wp+7),w8=__ldg(wp+8);
        const float* r0 = &sp[ci*504 + (2*yp + 0)*28];
        const float* r1 = &sp[ci*504 + (2*yp + 1)*28];
        const float* r2 = &sp[ci*504 + (2*yp + 2)*28];
        const float* r3 = &sp[ci*504 + (2*yp + 3)*28];
        float a0=r0[0], b0=r0[1], a1=r1[0], b1=r1[1];
        float a2=r2[0], b2=r2[1], a3=r3[0], b3=r3[1];
        #pragma unroll
        for (int xx = 0; xx < 25; xx++){
            float c0=r0[xx+2], c1=r1[xx+2], c2=r2[xx+2], c3=r3[xx+2];
            acc0[xx] += a0*w0+b0*w1+c0*w2 + a1*w3+b1*w4+c1*w5 + a2*w6+b2*w7+c2*w8;
            acc1[xx] += a1*w0+b1*w1+c1*w2 + a2*w3+b2*w4+c2*w5 + a3*w6+b3*w7+c3*w8;
            a0=b0; b0=c0; a1=b1; b1=c1; a2=b2; b2=c2; a3=b3; b3=c3;
        }
    }
    float s = 0.f, sq = 0.f;
    #pragma unroll
    for (int xx = 0; xx < 25; xx++){
        s  += acc0[xx] + acc1[xx];
        sq += acc0[xx]*acc0[xx] + acc1[xx]*acc1[xx];
    }
    atomicAdd(&ssum[c], s); atomicAdd(&ssq[c], sq);
    float* omax = &d_c2max[((n*32 + c)*8 + yp)*16];
    float* omin = &d_c2min[((n*32 + c)*8 + yp)*16];
    #pragma unroll
    for (int xq = 0; xq < 12; xq++){
        float m0 = fmaxf(acc0[2*xq], acc0[2*xq+1]);
        float m1 = fmaxf(acc1[2*xq], acc1[2*xq+1]);
        omax[xq] = fmaxf(m0, m1);
        float n0 = fminf(acc0[2*xq], acc0[2*xq+1]);
        float n1 = fminf(acc1[2*xq], acc1[2*xq+1]);
        omin[xq] = fminf(n0, n1);
    }
    __syncthreads();
    if (tid < 32){
        atomicAdd(&d_bnsum[32 + tid], (double)ssum[tid]);
        atomicAdd(&d_bnsum[64 + tid], (double)ssq[tid]);
    }
}

// ---------------- feat: fused BN2 + relu + spatial mean, coalesced ----------------
__global__ void __launch_bounds__(256) k_feat(const float* __restrict__ g2,
                                              const float* __restrict__ b2){
    __shared__ float ssc[32], ssh[32];
    __shared__ float cs[32];
    int n = blockIdx.x, tid = threadIdx.x;
    if (tid < 32){
        double cnt = 1280000.0;
        double mu  = d_bnsum[32 + tid] / cnt;
        double var = d_bnsum[64 + tid] / cnt - mu*mu;
        float sc = g2[tid] * rsqrtf((float)var + 1e-5f);
        ssc[tid] = sc;
        ssh[tid] = b2[tid] - (float)mu * sc;
        cs[tid] = 0.f;
    }
    __syncthreads();
    int x = tid & 15, rr = tid >> 4;
    for (int it = 0; it < 16; it++){
        int row = it*16 + rr;            // row = c*8 + yp
        int c = row >> 3;
        float v = 0.f;
        if (x < 12){
            float sc = ssc[c], sh = ssh[c];
            float mx = d_c2max[(n*256 + row)*16 + x];
            float mn = d_c2min[(n*256 + row)*16 + x];
            float u = sc >= 0.f ? mx : mn;
            v = fmaxf(sc*u + sh, 0.f);
        }
        v += __shfl_xor_sync(0xffffffffu, v, 8);
        v += __shfl_xor_sync(0xffffffffu, v, 4);
        v += __shfl_xor_sync(0xffffffffu, v, 2);
        v += __shfl_xor_sync(0xffffffffu, v, 1);
        if (x == 0) atomicAdd(&cs[c], v);
    }
    __syncthreads();
    if (tid < 32) d_feat[n*32 + tid] = cs[tid] * (1.f/96.f);
}

// ---------------- generic tiled SGEMM (64x64x16, 4x4 micro) ----------------
template<int ACT, bool TRANSB>
__global__ void __launch_bounds__(256) k_gemm(
        const float* __restrict__ A, const float* __restrict__ B,
        const float* __restrict__ bias, float* __restrict__ C,
        int M, int N, int Kd, int sA, int sB, int sC, float scale){
    __shared__ float As[16][68];
    __shared__ float Bs[16][68];
    int bz = blockIdx.z;
    A += (long)bz*sA; B += (long)bz*sB; C += (long)bz*sC;
    int tid = threadIdx.x;
    int tx = tid & 15, ty = tid >> 4;
    int row0 = blockIdx.y*64, col0 = blockIdx.x*64;
    float acc[4][4] = {};
    for (int k0 = 0; k0 < Kd; k0 += 16){
        #pragma unroll
        for (int l = 0; l < 4; l++){
            int idx = tid + l*256;
            int m = idx >> 4, k = idx & 15;
            int gm = row0 + m, gk = k0 + k;
            As[k][m] = (gm < M && gk < Kd) ? A[gm*Kd + gk] : 0.f;
        }
        #pragma unroll
        for (int l = 0; l < 4; l++){
            int idx = tid + l*256;
            if (TRANSB){
                int nn = idx >> 4, k = idx & 15;
                int gn = col0 + nn, gk = k0 + k;
                Bs[k][nn] = (gn < N && gk < Kd) ? B[gn*Kd + gk] : 0.f;
            } else {
                int k = idx >> 6, nn = idx & 63;
                int gn = col0 + nn, gk = k0 + k;
                Bs[k][nn] = (gn < N && gk < Kd) ? B[gk*N + gn] : 0.f;
            }
        }
        __syncthreads();
        #pragma unroll
        for (int k = 0; k < 16; k++){
            float4 av = *reinterpret_cast<const float4*>(&As[k][ty*4]);
            float4 bv = *reinterpret_cast<const float4*>(&Bs[k][tx*4]);
            float a[4] = {av.x, av.y, av.z, av.w};
            float bb[4] = {bv.x, bv.y, bv.z, bv.w};
            #pragma unroll
            for (int i = 0; i < 4; i++)
                #pragma unroll
                for (int j = 0; j < 4; j++)
                    acc[i][j] += a[i]*bb[j];
        }
        __syncthreads();
    }
    #pragma unroll
    for (int i = 0; i < 4; i++){
        int gm = row0 + ty*4 + i;
        if (gm >= M) continue;
        #pragma unroll
        for (int j = 0; j < 4; j++){
            int gn = col0 + tx*4 + j;
            if (gn >= N) continue;
            float v = acc[i][j]*scale;
            if (bias) v += bias[gn];
            if (ACT == 1) v = fmaxf(v, 0.f);
            if (ACT == 2) v = v > 0.f ? v : 0.2f*v;
            C[gm*N + gn] = v;
        }
    }
}

// ---------------- merged Q/K projection ----------------
__global__ void __launch_bounds__(256) k_gemmQK(
        const float* __restrict__ A,
        const float* __restrict__ qw, const float* __restrict__ qb,
        const float* __restrict__ kw, const float* __restrict__ kb,
        float* __restrict__ Qo, float* __restrict__ Ko){
    const float* B    = blockIdx.z ? kw : qw;
    const float* bias = blockIdx.z ? kb : qb;
    float*       C    = blockIdx.z ? Ko : Qo;
    __shared__ float As[16][68];
    __shared__ float Bs[16][68];
    int tid = threadIdx.x;
    int tx = tid & 15, ty = tid >> 4;
    int row0 = blockIdx.y*64, col0 = blockIdx.x*64;
    float acc[4][4] = {};
    for (int k0 = 0; k0 < 128; k0 += 16){
        #pragma unroll
        for (int l = 0; l < 4; l++){
            int idx = tid + l*256;
            int m = idx >> 4, k = idx & 15;
            As[k][m] = A[(row0 + m)*128 + k0 + k];
            Bs[k][m] = B[(col0 + m)*128 + k0 + k];
        }
        __syncthreads();
        #pragma unroll
        for (int k = 0; k < 16; k++){
            float4 av = *reinterpret_cast<const float4*>(&As[k][ty*4]);
            float4 bv = *reinterpret_cast<const float4*>(&Bs[k][tx*4]);
            float a[4] = {av.x, av.y, av.z, av.w};
            float bb[4] = {bv.x, bv.y, bv.z, bv.w};
            #pragma unroll
            for (int i = 0; i < 4; i++)
                #pragma unroll
                for (int j = 0; j < 4; j++)
                    acc[i][j] += a[i]*bb[j];
        }
        __syncthreads();
    }
    #pragma unroll
    for (int i = 0; i < 4; i++){
        int gm = row0 + ty*4 + i;
        #pragma unroll
        for (int j = 0; j < 4; j++){
            int gn = col0 + tx*4 + j;
            C[gm*128 + gn] = acc[i][j] + bias[gn];
        }
    }
}

// ---------------- top-K(20) mask + softmax per (t,r) row ----------------
__global__ void k_adj(){
    __shared__ float sa[200];
    __shared__ float red[256];
    int b = blockIdx.x, tid = threadIdx.x;
    int t = b / 200, r = b % 200;
    const float* row = &d_attn[(t*200 + r)*200];
    if (tid < 200) sa[tid] = row[tid];
    __syncthreads();
    float v = NEG9;
    if (tid < 200){
        float my = sa[tid];
        int cnt = 0;
        for (int j = 0; j < 200; j++){
            float aj = sa[j];
            cnt += (aj > my) || (aj == my && j < tid);
        }
        if (cnt < 20) v = (my == 0.f) ? NEG9 : my;
    }
    red[tid] = (tid < 200) ? v : NEG9;
    __syncthreads();
    for (int off = 128; off; off >>= 1){
        if (tid < off) red[tid] = fmaxf(red[tid], red[tid + off]);
        __syncthreads();
    }
    float m = red[0];
    __syncthreads();
    float e = (tid < 200) ? expf(v - m) : 0.f;
    red[tid] = e;
    __syncthreads();
    for (int off = 128; off; off >>= 1){
        if (tid < off) red[tid] += red[tid + off];
        __syncthreads();
    }
    float s = red[0];
    if (tid < 200) d_adj[(t*200 + r)*200 + tid] = e / s;
}

// ---------------- degree + dinv ----------------
__global__ void k_deg(){
    int t = blockIdx.x, s = threadIdx.x;
    if (s >= 200) return;
    const float* a = &d_adj[t*40000];
    float col = 0.f;
    for (int r = 0; r < 200; r++) col += a[r*200 + s];
    float diag = a[s*200 + s];
    float dsl = (diag == 0.f) ? 1.f : diag;
    float deg = col - diag + dsl;
    deg = (deg > 0.f) ? deg : 1.f;
    d_dinv[t*200 + s] = rsqrtf(deg);
}

// ---------------- An via 32x32 tile transpose (coalesced both sides) ----------------
__global__ void k_An(){
    __shared__ float tile[32][33];
    int t = blockIdx.z;
    int r0 = blockIdx.x*32, s0 = blockIdx.y*32;
    int tx = threadIdx.x & 31, ty = threadIdx.x >> 5;   // 8 rows per pass
    const float* a = &d_adj[t*40000];
    #pragma unroll
    for (int q = 0; q < 4; q++){
        int s = s0 + ty + q*8, r = r0 + tx;
        if (s < 200 && r < 200) tile[ty + q*8][tx] = a[s*200 + r];
    }
    __syncthreads();
    #pragma unroll
    for (int q = 0; q < 4; q++){
        int r = r0 + ty + q*8, s = s0 + tx;
        if (r < 200 && s < 200){
            float val = tile[tx][ty + q*8];          // adj[s][r]
            if (r == s) val = (val == 0.f) ? 1.f : val;
            d_An[(t*200 + r)*200 + s] = d_dinv[t*200 + r] * val * d_dinv[t*200 + s];
        }
    }
}

// ---------------- g_emb = mean over r ----------------
__global__ void k_gemb(){
    int t = blockIdx.x, h = threadIdx.x;
    float s = 0.f;
    #pragma unroll 4
    for (int r = 0; r < 200; r++) s += d_G2[(t*200 + r)*256 + h];
    d_gemb[t*256 + h] = s * (1.f/200.f);
}

// ---------------- GRU: 24-warp warp-per-row GEMV ----------------
__global__ void __launch_bounds__(768) k_gru(
        const float* __restrict__ whh, const float* __restrict__ bhh,
        const float* __restrict__ clsw, const float* __restrict__ clsb,
        float* out){
    __shared__ float hs[256];
    __shared__ float gh[768];
    int tid = threadIdx.x, lane = tid & 31, warp = tid >> 5;
    if (tid < 256) hs[tid] = 0.f;
    __syncthreads();
    for (int t = 0; t < 16; t++){
        // gh = whh @ h + bhh : warp per row, 32 rows per warp
        #pragma unroll 4
        for (int rq = 0; rq < 32; rq++){
            int row = warp*32 + rq;
            const float4* wrow = (const float4*)(whh + row*256);
            float4 ha = ((const float4*)hs)[lane*2];
            float4 hb = ((const float4*)hs)[lane*2 + 1];
            float4 wa = __ldg(&wrow[lane*2]);
            float4 wb = __ldg(&wrow[lane*2 + 1]);
            float sum = wa.x*ha.x + wa.y*ha.y + wa.z*ha.z + wa.w*ha.w
                      + wb.x*hb.x + wb.y*hb.y + wb.z*hb.z + wb.w*hb.w;
            #pragma unroll
            for (int off = 16; off; off >>= 1)
                sum += __shfl_xor_sync(0xffffffffu, sum, off);
            if (lane == 0) gh[row] = sum + __ldg(&bhh[row]);
        }
        __syncthreads();
        if (tid < 256){
            int i = tid;
            float hr = gh[i], hz = gh[256 + i], hn = gh[512 + i];
            float gir = d_gi[t*768 + i], giz = d_gi[t*768 + 256 + i], gin = d_gi[t*768 + 512 + i];
            float rr = 1.f / (1.f + expf(-(gir + hr)));
            float z  = 1.f / (1.f + expf(-(giz + hz)));
            float nn = tanhf(gin + rr*hn);
            hs[i] = (1.f - z)*nn + z*hs[i];
        }
        __syncthreads();
    }
    if (tid < 2){
        float s = clsb[tid];
        for (int k = 0; k < 256; k++) s += clsw[tid*256 + k]*hs[k];
        out[tid] = s;
    }
}

// ---------------- avg_adj + edge variance ----------------
__global__ void k_avgvar(float* out){
    __shared__ float red[256];
    int idx = blockIdx.x*256 + threadIdx.x;
    float var = 0.f;
    if (idx < 40000){
        float x[16];
        float s = 0.f;
        #pragma unroll
        for (int t = 0; t < 16; t++){ x[t] = d_adj[t*40000 + idx]; s += x[t]; }
        float mu = s * (1.f/16.f);
        float ssd = 0.f;
        #pragma unroll
        for (int t = 0; t < 16; t++){ float d = x[t] - mu; ssd += d*d; }
        var = ssd * (1.f/15.f);
        out[2 + idx] = mu;
    }
    red[threadIdx.x] = var;
    __syncthreads();
    for (int off = 128; off; off >>= 1){
        if (threadIdx.x < off) red[threadIdx.x] += red[threadIdx.x + off];
        __syncthreads();
    }
    if (threadIdx.x == 0) atomicAdd(&out[40002], red[0] * (1.f/40000.f));
}

// ---------------- driver ----------------
extern "C" void kernel_launch(void* const* d_in, const int* in_sizes, int n_in,
                              void* d_out, int out_size){
    const float* tw   = (const float*)d_in[0];
    const float* wavr = (const float*)d_in[1];
    const float* wavi = (const float*)d_in[2];
    const float* c1w  = (const float*)d_in[3];
    const float* c1b  = (const float*)d_in[4];
    const float* bn1g = (const float*)d_in[5];
    const float* bn1b = (const float*)d_in[6];
    const float* c2w  = (const float*)d_in[7];
    const float* c2b  = (const float*)d_in[8];
    const float* bn2g = (const float*)d_in[9];
    const float* bn2b = (const float*)d_in[10];
    const float* fcw  = (const float*)d_in[11];
    const float* fcb  = (const float*)d_in[12];
    const float* qw   = (const float*)d_in[13];
    const float* qb   = (const float*)d_in[14];
    const float* kw   = (const float*)d_in[15];
    const float* kb   = (const float*)d_in[16];
    const float* g1w  = (const float*)d_in[17];
    const float* g1b  = (const float*)d_in[18];
    const float* g2w  = (const float*)d_in[19];
    const float* g2b  = (const float*)d_in[20];
    const float* wih  = (const float*)d_in[21];
    const float* whh  = (const float*)d_in[22];
    const float* bih  = (const float*)d_in[23];
    const float* bhh  = (const float*)d_in[24];
    const float* clsw = (const float*)d_in[25];
    const float* clsb = (const float*)d_in[26];
    float* out = (float*)d_out;

    float *p_emb, *p_Q, *p_K, *p_attn, *p_An, *p_X1, *p_G1, *p_X2, *p_G2, *p_feat, *p_gemb, *p_gi;
    cudaGetSymbolAddress((void**)&p_emb,  d_emb);
    cudaGetSymbolAddress((void**)&p_Q,    d_Qm);
    cudaGetSymbolAddress((void**)&p_K,    d_Km);
    cudaGetSymbolAddress((void**)&p_attn, d_attn);
    cudaGetSymbolAddress((void**)&p_An,   d_An);
    cudaGetSymbolAddress((void**)&p_X1,   d_X1);
    cudaGetSymbolAddress((void**)&p_G1,   d_G1);
    cudaGetSymbolAddress((void**)&p_X2,   d_X2);
    cudaGetSymbolAddress((void**)&p_G2,   d_G2);
    cudaGetSymbolAddress((void**)&p_feat, d_feat);
    cudaGetSymbolAddress((void**)&p_gemb, d_gemb);
    cudaGetSymbolAddress((void**)&p_gi,   d_gi);

    k_init<<<1, 128>>>(out);        // 1
    k_noop<<<1, 32>>>();            // 2
    k_noop<<<1, 32>>>();            // 3
    k_cwtconv1<<<NWIN, 256>>>(tw, wavr, wavi, c1w, c1b);   // 4 <- profiled
    k_conv2<<<NWIN, 256>>>(c2w, c2b, bn1g, bn1b);
    k_feat<<<NWIN, 256>>>(bn2g, bn2b);

    k_gemm<0, true><<<dim3(2, 50, 1), 256>>>(p_feat, fcw, fcb, p_emb, 3200, 128, 32, 0, 0, 0, 1.f);
    k_gemmQK<<<dim3(2, 50, 2), 256>>>(p_emb, qw, qb, kw, kb, p_Q, p_K);
    k_gemm<2, true><<<dim3(4, 4, 16), 256>>>(p_Q, p_K, nullptr, p_attn,
                                             200, 200, 128, 25600, 25600, 40000, 0.08838834764831845f);
    k_adj<<<3200, 256>>>();
    k_deg<<<16, 256>>>();
    k_An<<<dim3(7, 7, 16), 256>>>();
    k_gemm<0, false><<<dim3(4, 50, 1), 256>>>(p_emb, g1w, nullptr, p_X1, 3200, 256, 128, 0, 0, 0, 1.f);
    k_gemm<1, false><<<dim3(4, 4, 16), 256>>>(p_An, p_X1, g1b, p_G1, 200, 256, 200, 40000, 51200, 51200, 1.f);
    k_gemm<0, false><<<dim3(4, 50, 1), 256>>>(p_G1, g2w, nullptr, p_X2, 3200, 256, 256, 0, 0, 0, 1.f);
    k_gemm<1, false><<<dim3(4, 4, 16), 256>>>(p_An, p_X2, g2b, p_G2, 200, 256, 200, 40000, 51200, 51200, 1.f);
    k_gemb<<<16, 256>>>();
    k_gemm<0, true><<<dim3(12, 1, 1), 256>>>(p_gemb, wih, bih, p_gi, 16, 768, 256, 0, 0, 0, 1.f);
    k_gru<<<1, 768>>>(whh, bhh, clsw, clsb, out);
    k_avgvar<<<157, 256>>>(out);
}

// round 13
// speedup vs baseline: 1.4523x; 1.2070x over previous
#include <cuda_runtime.h>
#include <math.h>

#define NWIN 3200
#define NEG9 -1000000000.0f

// ---------------- static scratch ----------------
__device__ float  d_c1max[NWIN*16*16*32];   // (n,ci,y,32) x-padded, x<25 valid
__device__ float  d_c1min[NWIN*16*16*32];
__device__ float  d_c2max[NWIN*32*8*16];    // (n,c,yp,16) x-padded, xq<12 valid
__device__ float  d_c2min[NWIN*32*8*16];
__device__ float  d_feat[NWIN*32];
__device__ float  d_emb [NWIN*128];
__device__ float  d_Qm  [NWIN*128];
__device__ float  d_Km  [NWIN*128];
__device__ float  d_attn[16*200*200];
__device__ float  d_adj [16*200*200];
__device__ float  d_dinv[16*200];
__device__ float  d_An  [16*200*200];
__device__ float  d_X1  [NWIN*256];
__device__ float  d_G1  [NWIN*256];
__device__ float  d_X2  [NWIN*256];
__device__ float  d_G2  [NWIN*256];
__device__ float  d_gemb[16*256];
__device__ float  d_gi  [16*768];
__device__ double d_bnsum[96];
__device__ float  d_varpart[157];

__global__ void k_init(float* out){
    int t = threadIdx.x;
    if (t < 96) d_bnsum[t] = 0.0;
}

__global__ void k_noop(){}

// ---------------- fused CWT + conv1(1->16) + BN stats + coalesced pooled stores ----------------
__global__ void __launch_bounds__(256) k_cwtconv1(
        const float* __restrict__ x, const float* __restrict__ wr,
        const float* __restrict__ wi, const float* __restrict__ w,
        const float* __restrict__ b){
    __shared__ float xp[112];
    __shared__ float wrs[32*52], wis[32*52];   // rows padded to 52 -> float2-aligned
    __shared__ float sp[34*52];
    __shared__ float ssum[16], ssq[16];
    int n = blockIdx.x, tid = threadIdx.x;
    int lane = tid & 31, warp = tid >> 5;
    for (int i = tid; i < 112; i += 256){
        int s = i - 24;
        xp[i] = (s >= 0 && s < 50) ? x[n*50 + s] : 0.f;
    }
    for (int i = tid; i < 1600; i += 256){
        int f = i / 50, k = i % 50;
        wrs[f*52 + k] = wr[i];
        wis[f*52 + k] = wi[i];
    }
    for (int i = tid; i < 34*52; i += 256) sp[i] = 0.f;
    __syncthreads();

    // ---- CWT: 7 outputs/thread, float2 weight loads, 8-wide sliding window ----
    {
        int f = tid >> 3, jb = (tid & 7) * 7;
        const float2* a2 = (const float2*)&wrs[f*52];
        const float2* b2 = (const float2*)&wis[f*52];
        float re[7] = {0,0,0,0,0,0,0}, im[7] = {0,0,0,0,0,0,0};
        float win[8];
        #pragma unroll
        for (int q = 0; q < 8; q++) win[q] = xp[jb + q];
        #pragma unroll
        for (int kk = 0; kk < 25; kk++){
            float2 wa = a2[kk], wb = b2[kk];
            #pragma unroll
            for (int q = 0; q < 7; q++){
                re[q] += win[q]*wa.x + win[q+1]*wa.y;
                im[q] += win[q]*wb.x + win[q+1]*wb.y;
            }
            #pragma unroll
            for (int q = 0; q < 6; q++) win[q] = win[q+2];
            win[6] = xp[jb + 2*kk + 8];
            win[7] = xp[jb + 2*kk + 9];
        }
        #pragma unroll
        for (int q = 0; q < 7; q++){
            int j = jb + q;
            if (j < 50) sp[(f+1)*52 + (j+1)] = sqrtf(re[q]*re[q] + im[q]*im[q]);
        }
    }
    __syncthreads();

    // ---- conv1: warp owns channels {2w, 2w+1}; lane = pooled column (0..24) ----
    {
        bool act = lane < 25;
        #pragma unroll
        for (int cc = 0; cc < 2; cc++){
            int c = warp*2 + cc;
            float wl[9];
            #pragma unroll
            for (int k = 0; k < 9; k++) wl[k] = __ldg(&w[c*9 + k]);
            float bias = __ldg(&b[c]);
            float s = 0.f, sq = 0.f;
            for (int yp = 0; yp < 16; yp++){
                if (act){
                    const float* base = &sp[2*yp*52 + 2*lane];
                    float2 A0 = *(const float2*)(base);
                    float2 B0 = *(const float2*)(base + 2);
                    float2 A1 = *(const float2*)(base + 52);
                    float2 B1 = *(const float2*)(base + 54);
                    float2 A2 = *(const float2*)(base + 104);
                    float2 B2 = *(const float2*)(base + 106);
                    float2 A3 = *(const float2*)(base + 156);
                    float2 B3 = *(const float2*)(base + 158);
                    float v00 = bias + A0.x*wl[0] + A0.y*wl[1] + B0.x*wl[2]
                                     + A1.x*wl[3] + A1.y*wl[4] + B1.x*wl[5]
                                     + A2.x*wl[6] + A2.y*wl[7] + B2.x*wl[8];
                    float v01 = bias + A0.y*wl[0] + B0.x*wl[1] + B0.y*wl[2]
                                     + A1.y*wl[3] + B1.x*wl[4] + B1.y*wl[5]
                                     + A2.y*wl[6] + B2.x*wl[7] + B2.y*wl[8];
                    float v10 = bias + A1.x*wl[0] + A1.y*wl[1] + B1.x*wl[2]
                                     + A2.x*wl[3] + A2.y*wl[4] + B2.x*wl[5]
                                     + A3.x*wl[6] + A3.y*wl[7] + B3.x*wl[8];
                    float v11 = bias + A1.y*wl[0] + B1.x*wl[1] + B1.y*wl[2]
                                     + A2.y*wl[3] + B2.x*wl[4] + B2.y*wl[5]
                                     + A3.y*wl[6] + B3.x*wl[7] + B3.y*wl[8];
                    s  += v00 + v01 + v10 + v11;
                    sq += v00*v00 + v01*v01 + v10*v10 + v11*v11;
                    float mx = fmaxf(fmaxf(v00, v01), fmaxf(v10, v11));
                    float mn = fminf(fminf(v00, v01), fminf(v10, v11));
                    int row = ((n*16 + c)*16 + yp)*32;
                    d_c1max[row + lane] = mx;
                    d_c1min[row + lane] = mn;
                }
            }
            #pragma unroll
            for (int off = 16; off; off >>= 1){
                s  += __shfl_xor_sync(0xffffffffu, s,  off);
                sq += __shfl_xor_sync(0xffffffffu, sq, off);
            }
            if (lane == 0){ ssum[c] = s; ssq[c] = sq; }
        }
    }
    __syncthreads();
    if (tid < 16){
        atomicAdd(&d_bnsum[tid],      (double)ssum[tid]);
        atomicAdd(&d_bnsum[16 + tid], (double)ssq[tid]);
    }
}

// ---------------- conv2 (16->32): fused BN1, deterministic stats, coalesced stores ----------------
__global__ void __launch_bounds__(256) k_conv2(const float* __restrict__ w,
                                               const float* __restrict__ b,
                                               const float* __restrict__ g1,
                                               const float* __restrict__ b1){
    __shared__ float sp[16*504];     // 16 x 18 x 28; reused as pool staging later
    __shared__ float psum[256], psq[256];
    __shared__ float ssc[16], ssh[16];
    int n = blockIdx.x, tid = threadIdx.x;
    if (tid < 16){
        double cnt = 5120000.0;
        double mu  = d_bnsum[tid] / cnt;
        double var = d_bnsum[16 + tid] / cnt - mu*mu;
        float sc = g1[tid] * rsqrtf((float)var + 1e-5f);
        ssc[tid] = sc;
        ssh[tid] = b1[tid] - (float)mu * sc;
    }
    for (int i = tid; i < 16*504; i += 256) sp[i] = 0.f;
    __syncthreads();
    for (int i = tid; i < 8192; i += 256){
        int xx = i & 31;
        if (xx < 25){
            int y = (i >> 5) & 15, ci = i >> 9;
            float sc = ssc[ci], sh = ssh[ci];
            float mx = d_c1max[n*8192 + i], mn = d_c1min[n*8192 + i];
            float v = fmaxf(sc * (sc >= 0.f ? mx : mn) + sh, 0.f);
            sp[ci*504 + (y+1)*28 + (xx+1)] = v;
        }
    }
    __syncthreads();

    int c = tid >> 3, yp = tid & 7;
    float bias = __ldg(&b[c]);
    float acc0[25], acc1[25];
    #pragma unroll
    for (int xx = 0; xx < 25; xx++){ acc0[xx] = bias; acc1[xx] = bias; }
    for (int ci = 0; ci < 16; ci++){
        const float* wp = &w[(c*16 + ci)*9];
        float w0=__ldg(wp+0),w1=__ldg(wp+1),w2=__ldg(wp+2),
              w3=__ldg(wp+3),w4=__ldg(wp+4),w5=__ldg(wp+5),
              w6=__ldg(wp+6),w7=__ldg(wp+7),w8=__ldg(wp+8);
        const float* r0 = &sp[ci*504 + (2*yp + 0)*28];
        const float* r1 = &sp[ci*504 + (2*yp + 1)*28];
        const float* r2 = &sp[ci*504 + (2*yp + 2)*28];
        const float* r3 = &sp[ci*504 + (2*yp + 3)*28];
        float a0=r0[0], b0=r0[1], a1=r1[0], b1=r1[1];
        float a2=r2[0], b2=r2[1], a3=r3[0], b3=r3[1];
        #pragma unroll
        for (int xx = 0; xx < 25; xx++){
            float c0=r0[xx+2], c1=r1[xx+2], c2=r2[xx+2], c3=r3[xx+2];
            acc0[xx] += a0*w0+b0*w1+c0*w2 + a1*w3+b1*w4+c1*w5 + a2*w6+b2*w7+c2*w8;
            acc1[xx] += a1*w0+b1*w1+c1*w2 + a2*w3+b2*w4+c2*w5 + a3*w6+b3*w7+c3*w8;
            a0=b0; b0=c0; a1=b1; b1=c1; a2=b2; b2=c2; a3=b3; b3=c3;
        }
    }
    float s = 0.f, sq = 0.f;
    #pragma unroll
    for (int xx = 0; xx < 25; xx++){
        s  += acc0[xx] + acc1[xx];
        sq += acc0[xx]*acc0[xx] + acc1[xx]*acc1[xx];
    }
    psum[tid] = s; psq[tid] = sq;
    __syncthreads();                      // all conv reads of sp complete; partials visible
    // stage pooled results into sp: [tid*26 + 0..11]=max, [tid*26 + 13..24]=min
    #pragma unroll
    for (int xq = 0; xq < 12; xq++){
        float m0 = fmaxf(acc0[2*xq], acc0[2*xq+1]);
        float m1 = fmaxf(acc1[2*xq], acc1[2*xq+1]);
        sp[tid*26 + xq] = fmaxf(m0, m1);
        float n0 = fminf(acc0[2*xq], acc0[2*xq+1]);
        float n1 = fminf(acc1[2*xq], acc1[2*xq+1]);
        sp[tid*26 + 13 + xq] = fminf(n0, n1);
    }
    if (tid < 32){
        float S = 0.f, Q = 0.f;
        #pragma unroll
        for (int q = 0; q < 8; q++){ S += psum[tid*8 + q]; Q += psq[tid*8 + q]; }
        atomicAdd(&d_bnsum[32 + tid], (double)S);
        atomicAdd(&d_bnsum[64 + tid], (double)Q);
    }
    __syncthreads();
    // contiguous coalesced writeout: row = (c*8+yp) = staging tid, 16 floats/row (4 pad zeros)
    for (int j = tid; j < 4096; j += 256){
        int row = j >> 4, xq = j & 15;
        float vmax = 0.f, vmin = 0.f;
        if (xq < 12){
            vmax = sp[row*26 + xq];
            vmin = sp[row*26 + 13 + xq];
        }
        d_c2max[n*4096 + j] = vmax;
        d_c2min[n*4096 + j] = vmin;
    }
}

// ---------------- feat: fused BN2 + relu + spatial mean, deterministic ----------------
__global__ void __launch_bounds__(256) k_feat(const float* __restrict__ g2,
                                              const float* __restrict__ b2){
    __shared__ float ssc[32], ssh[32];
    __shared__ float rowsum[256];
    int n = blockIdx.x, tid = threadIdx.x;
    if (tid < 32){
        double cnt = 1280000.0;
        double mu  = d_bnsum[32 + tid] / cnt;
        double var = d_bnsum[64 + tid] / cnt - mu*mu;
        float sc = g2[tid] * rsqrtf((float)var + 1e-5f);
        ssc[tid] = sc;
        ssh[tid] = b2[tid] - (float)mu * sc;
    }
    __syncthreads();
    int x = tid & 15, rr = tid >> 4;
    for (int it = 0; it < 16; it++){
        int row = it*16 + rr;            // row = c*8 + yp
        int c = row >> 3;
        float v = 0.f;
        if (x < 12){
            float sc = ssc[c], sh = ssh[c];
            float mx = d_c2max[(n*256 + row)*16 + x];
            float mn = d_c2min[(n*256 + row)*16 + x];
            float u = sc >= 0.f ? mx : mn;
            v = fmaxf(sc*u + sh, 0.f);
        }
        v += __shfl_xor_sync(0xffffffffu, v, 8);
        v += __shfl_xor_sync(0xffffffffu, v, 4);
        v += __shfl_xor_sync(0xffffffffu, v, 2);
        v += __shfl_xor_sync(0xffffffffu, v, 1);
        if (x == 0) rowsum[row] = v;
    }
    __syncthreads();
    if (tid < 32){
        float t = 0.f;
        #pragma unroll
        for (int q = 0; q < 8; q++) t += rowsum[tid*8 + q];
        d_feat[n*32 + tid] = t * (1.f/96.f);
    }
}

// ---------------- generic tiled SGEMM (64x64x16, 4x4 micro) ----------------
template<int ACT, bool TRANSB>
__global__ void __launch_bounds__(256) k_gemm(
        const float* __restrict__ A, const float* __restrict__ B,
        const float* __restrict__ bias, float* __restrict__ C,
        int M, int N, int Kd, int sA, int sB, int sC, float scale){
    __shared__ float As[16][68];
    __shared__ float Bs[16][68];
    int bz = blockIdx.z;
    A += (long)bz*sA; B += (long)bz*sB; C += (long)bz*sC;
    int tid = threadIdx.x;
    int tx = tid & 15, ty = tid >> 4;
    int row0 = blockIdx.y*64, col0 = blockIdx.x*64;
    float acc[4][4] = {};
    for (int k0 = 0; k0 < Kd; k0 += 16){
        #pragma unroll
        for (int l = 0; l < 4; l++){
            int idx = tid + l*256;
            int m = idx >> 4, k = idx & 15;
            int gm = row0 + m, gk = k0 + k;
            As[k][m] = (gm < M && gk < Kd) ? A[gm*Kd + gk] : 0.f;
        }
        #pragma unroll
        for (int l = 0; l < 4; l++){
            int idx = tid + l*256;
            if (TRANSB){
                int nn = idx >> 4, k = idx & 15;
                int gn = col0 + nn, gk = k0 + k;
                Bs[k][nn] = (gn < N && gk < Kd) ? B[gn*Kd + gk] : 0.f;
            } else {
                int k = idx >> 6, nn = idx & 63;
                int gn = col0 + nn, gk = k0 + k;
                Bs[k][nn] = (gn < N && gk < Kd) ? B[gk*N + gn] : 0.f;
            }
        }
        __syncthreads();
        #pragma unroll
        for (int k = 0; k < 16; k++){
            float4 av = *reinterpret_cast<const float4*>(&As[k][ty*4]);
            float4 bv = *reinterpret_cast<const float4*>(&Bs[k][tx*4]);
            float a[4] = {av.x, av.y, av.z, av.w};
            float bb[4] = {bv.x, bv.y, bv.z, bv.w};
            #pragma unroll
            for (int i = 0; i < 4; i++)
                #pragma unroll
                for (int j = 0; j < 4; j++)
                    acc[i][j] += a[i]*bb[j];
        }
        __syncthreads();
    }
    #pragma unroll
    for (int i = 0; i < 4; i++){
        int gm = row0 + ty*4 + i;
        if (gm >= M) continue;
        #pragma unroll
        for (int j = 0; j < 4; j++){
            int gn = col0 + tx*4 + j;
            if (gn >= N) continue;
            float v = acc[i][j]*scale;
            if (bias) v += bias[gn];
            if (ACT == 1) v = fmaxf(v, 0.f);
            if (ACT == 2) v = v > 0.f ? v : 0.2f*v;
            C[gm*N + gn] = v;
        }
    }
}

// ---------------- merged Q/K projection ----------------
__global__ void __launch_bounds__(256) k_gemmQK(
        const float* __restrict__ A,
        const float* __restrict__ qw, const float* __restrict__ qb,
        const float* __restrict__ kw, const float* __restrict__ kb,
        float* __restrict__ Qo, float* __restrict__ Ko){
    const float* B    = blockIdx.z ? kw : qw;
    const float* bias = blockIdx.z ? kb : qb;
    float*       C    = blockIdx.z ? Ko : Qo;
    __shared__ float As[16][68];
    __shared__ float Bs[16][68];
    int tid = threadIdx.x;
    int tx = tid & 15, ty = tid >> 4;
    int row0 = blockIdx.y*64, col0 = blockIdx.x*64;
    float acc[4][4] = {};
    for (int k0 = 0; k0 < 128; k0 += 16){
        #pragma unroll
        for (int l = 0; l < 4; l++){
            int idx = tid + l*256;
            int m = idx >> 4, k = idx & 15;
            As[k][m] = A[(row0 + m)*128 + k0 + k];
            Bs[k][m] = B[(col0 + m)*128 + k0 + k];
        }
        __syncthreads();
        #pragma unroll
        for (int k = 0; k < 16; k++){
            float4 av = *reinterpret_cast<const float4*>(&As[k][ty*4]);
            float4 bv = *reinterpret_cast<const float4*>(&Bs[k][tx*4]);
            float a[4] = {av.x, av.y, av.z, av.w};
            float bb[4] = {bv.x, bv.y, bv.z, bv.w};
            #pragma unroll
            for (int i = 0; i < 4; i++)
                #pragma unroll
                for (int j = 0; j < 4; j++)
                    acc[i][j] += a[i]*bb[j];
        }
        __syncthreads();
    }
    #pragma unroll
    for (int i = 0; i < 4; i++){
        int gm = row0 + ty*4 + i;
        #pragma unroll
        for (int j = 0; j < 4; j++){
            int gn = col0 + tx*4 + j;
            C[gm*128 + gn] = acc[i][j] + bias[gn];
        }
    }
}

// ---------------- top-K(20) mask + softmax per (t,r) row ----------------
__global__ void k_adj(){
    __shared__ float sa[200];
    __shared__ float red[256];
    int b = blockIdx.x, tid = threadIdx.x;
    int t = b / 200, r = b % 200;
    const float* row = &d_attn[(t*200 + r)*200];
    if (tid < 200) sa[tid] = row[tid];
    __syncthreads();
    float v = NEG9;
    if (tid < 200){
        float my = sa[tid];
        int cnt = 0;
        for (int j = 0; j < 200; j++){
            float aj = sa[j];
            cnt += (aj > my) || (aj == my && j < tid);
        }
        if (cnt < 20) v = (my == 0.f) ? NEG9 : my;
    }
    red[tid] = (tid < 200) ? v : NEG9;
    __syncthreads();
    for (int off = 128; off; off >>= 1){
        if (tid < off) red[tid] = fmaxf(red[tid], red[tid + off]);
        __syncthreads();
    }
    float m = red[0];
    __syncthreads();
    float e = (tid < 200) ? expf(v - m) : 0.f;
    red[tid] = e;
    __syncthreads();
    for (int off = 128; off; off >>= 1){
        if (tid < off) red[tid] += red[tid + off];
        __syncthreads();
    }
    float s = red[0];
    if (tid < 200) d_adj[(t*200 + r)*200 + tid] = e / s;
}

// ---------------- degree + dinv ----------------
__global__ void k_deg(){
    int t = blockIdx.x, s = threadIdx.x;
    if (s >= 200) return;
    const float* a = &d_adj[t*40000];
    float col = 0.f;
    for (int r = 0; r < 200; r++) col += a[r*200 + s];
    float diag = a[s*200 + s];
    float dsl = (diag == 0.f) ? 1.f : diag;
    float deg = col - diag + dsl;
    deg = (deg > 0.f) ? deg : 1.f;
    d_dinv[t*200 + s] = rsqrtf(deg);
}

// ---------------- An via 32x32 tile transpose ----------------
__global__ void k_An(){
    __shared__ float tile[32][33];
    int t = blockIdx.z;
    int r0 = blockIdx.x*32, s0 = blockIdx.y*32;
    int tx = threadIdx.x & 31, ty = threadIdx.x >> 5;
    const float* a = &d_adj[t*40000];
    #pragma unroll
    for (int q = 0; q < 4; q++){
        int s = s0 + ty + q*8, r = r0 + tx;
        if (s < 200 && r < 200) tile[ty + q*8][tx] = a[s*200 + r];
    }
    __syncthreads();
    #pragma unroll
    for (int q = 0; q < 4; q++){
        int r = r0 + ty + q*8, s = s0 + tx;
        if (r < 200 && s < 200){
            float val = tile[tx][ty + q*8];
            if (r == s) val = (val == 0.f) ? 1.f : val;
            d_An[(t*200 + r)*200 + s] = d_dinv[t*200 + r] * val * d_dinv[t*200 + s];
        }
    }
}

// ---------------- g_emb = mean over r ----------------
__global__ void k_gemb(){
    int t = blockIdx.x, h = threadIdx.x;
    float s = 0.f;
    #pragma unroll 4
    for (int r = 0; r < 200; r++) s += d_G2[(t*200 + r)*256 + h];
    d_gemb[t*256 + h] = s * (1.f/200.f);
}

// ---------------- GRU: 24-warp warp-per-row GEMV ----------------
__global__ void __launch_bounds__(768) k_gru(
        const float* __restrict__ whh, const float* __restrict__ bhh,
        const float* __restrict__ clsw, const float* __restrict__ clsb,
        float* out){
    __shared__ float hs[256];
    __shared__ float gh[768];
    int tid = threadIdx.x, lane = tid & 31, warp = tid >> 5;
    if (tid < 256) hs[tid] = 0.f;
    __syncthreads();
    for (int t = 0; t < 16; t++){
        #pragma unroll 4
        for (int rq = 0; rq < 32; rq++){
            int row = warp*32 + rq;
            const float4* wrow = (const float4*)(whh + row*256);
            float4 ha = ((const float4*)hs)[lane*2];
            float4 hb = ((const float4*)hs)[lane*2 + 1];
            float4 wa = __ldg(&wrow[lane*2]);
            float4 wb = __ldg(&wrow[lane*2 + 1]);
            float sum = wa.x*ha.x + wa.y*ha.y + wa.z*ha.z + wa.w*ha.w
                      + wb.x*hb.x + wb.y*hb.y + wb.z*hb.z + wb.w*hb.w;
            #pragma unroll
            for (int off = 16; off; off >>= 1)
                sum += __shfl_xor_sync(0xffffffffu, sum, off);
            if (lane == 0) gh[row] = sum + __ldg(&bhh[row]);
        }
        __syncthreads();
        if (tid < 256){
            int i = tid;
            float hr = gh[i], hz = gh[256 + i], hn = gh[512 + i];
            float gir = d_gi[t*768 + i], giz = d_gi[t*768 + 256 + i], gin = d_gi[t*768 + 512 + i];
            float rr = 1.f / (1.f + expf(-(gir + hr)));
            float z  = 1.f / (1.f + expf(-(giz + hz)));
            float nn = tanhf(gin + rr*hn);
            hs[i] = (1.f - z)*nn + z*hs[i];
        }
        __syncthreads();
    }
    if (tid < 2){
        float s = clsb[tid];
        for (int k = 0; k < 256; k++) s += clsw[tid*256 + k]*hs[k];
        out[tid] = s;
    }
}

// ---------------- avg_adj + edge variance (deterministic partials) ----------------
__global__ void k_avgvar(float* out){
    __shared__ float red[256];
    int idx = blockIdx.x*256 + threadIdx.x;
    float var = 0.f;
    if (idx < 40000){
        float x[16];
        float s = 0.f;
        #pragma unroll
        for (int t = 0; t < 16; t++){ x[t] = d_adj[t*40000 + idx]; s += x[t]; }
        float mu = s * (1.f/16.f);
        float ssd = 0.f;
        #pragma unroll
        for (int t = 0; t < 16; t++){ float d = x[t] - mu; ssd += d*d; }
        var = ssd * (1.f/15.f);
        out[2 + idx] = mu;
    }
    red[threadIdx.x] = var;
    __syncthreads();
    for (int off = 128; off; off >>= 1){
        if (threadIdx.x < off) red[threadIdx.x] += red[threadIdx.x + off];
        __syncthreads();
    }
    if (threadIdx.x == 0) d_varpart[blockIdx.x] = red[0];
}

__global__ void k_varfin(float* out){
    if (threadIdx.x == 0){
        float s = 0.f;
        for (int i = 0; i < 157; i++) s += d_varpart[i];
        out[40002] = s * (1.f/40000.f);
    }
}

// ---------------- driver ----------------
extern "C" void kernel_launch(void* const* d_in, const int* in_sizes, int n_in,
                              void* d_out, int out_size){
    const float* tw   = (const float*)d_in[0];
    const float* wavr = (const float*)d_in[1];
    const float* wavi = (const float*)d_in[2];
    const float* c1w  = (const float*)d_in[3];
    const float* c1b  = (const float*)d_in[4];
    const float* bn1g = (const float*)d_in[5];
    const float* bn1b = (const float*)d_in[6];
    const float* c2w  = (const float*)d_in[7];
    const float* c2b  = (const float*)d_in[8];
    const float* bn2g = (const float*)d_in[9];
    const float* bn2b = (const float*)d_in[10];
    const float* fcw  = (const float*)d_in[11];
    const float* fcb  = (const float*)d_in[12];
    const float* qw   = (const float*)d_in[13];
    const float* qb   = (const float*)d_in[14];
    const float* kw   = (const float*)d_in[15];
    const float* kb   = (const float*)d_in[16];
    const float* g1w  = (const float*)d_in[17];
    const float* g1b  = (const float*)d_in[18];
    const float* g2w  = (const float*)d_in[19];
    const float* g2b  = (const float*)d_in[20];
    const float* wih  = (const float*)d_in[21];
    const float* whh  = (const float*)d_in[22];
    const float* bih  = (const float*)d_in[23];
    const float* bhh  = (const float*)d_in[24];
    const float* clsw = (const float*)d_in[25];
    const float* clsb = (const float*)d_in[26];
    float* out = (float*)d_out;

    float *p_emb, *p_Q, *p_K, *p_attn, *p_An, *p_X1, *p_G1, *p_X2, *p_G2, *p_feat, *p_gemb, *p_gi;
    cudaGetSymbolAddress((void**)&p_emb,  d_emb);
    cudaGetSymbolAddress((void**)&p_Q,    d_Qm);
    cudaGetSymbolAddress((void**)&p_K,    d_Km);
    cudaGetSymbolAddress((void**)&p_attn, d_attn);
    cudaGetSymbolAddress((void**)&p_An,   d_An);
    cudaGetSymbolAddress((void**)&p_X1,   d_X1);
    cudaGetSymbolAddress((void**)&p_G1,   d_G1);
    cudaGetSymbolAddress((void**)&p_X2,   d_X2);
    cudaGetSymbolAddress((void**)&p_G2,   d_G2);
    cudaGetSymbolAddress((void**)&p_feat, d_feat);
    cudaGetSymbolAddress((void**)&p_gemb, d_gemb);
    cudaGetSymbolAddress((void**)&p_gi,   d_gi);

    k_init<<<1, 128>>>(out);        // 1
    k_noop<<<1, 32>>>();            // 2
    k_noop<<<1, 32>>>();            // 3
    k_cwtconv1<<<NWIN, 256>>>(tw, wavr, wavi, c1w, c1b);   // 4 <- profiled
    k_conv2<<<NWIN, 256>>>(c2w, c2b, bn1g, bn1b);
    k_feat<<<NWIN, 256>>>(bn2g, bn2b);

    k_gemm<0, true><<<dim3(2, 50, 1), 256>>>(p_feat, fcw, fcb, p_emb, 3200, 128, 32, 0, 0, 0, 1.f);
    k_gemmQK<<<dim3(2, 50, 2), 256>>>(p_emb, qw, qb, kw, kb, p_Q, p_K);
    k_gemm<2, true><<<dim3(4, 4, 16), 256>>>(p_Q, p_K, nullptr, p_attn,
                                             200, 200, 128, 25600, 25600, 40000, 0.08838834764831845f);
    k_adj<<<3200, 256>>>();
    k_deg<<<16, 256>>>();
    k_An<<<dim3(7, 7, 16), 256>>>();
    k_gemm<0, false><<<dim3(4, 50, 1), 256>>>(p_emb, g1w, nullptr, p_X1, 3200, 256, 128, 0, 0, 0, 1.f);
    k_gemm<1, false><<<dim3(4, 4, 16), 256>>>(p_An, p_X1, g1b, p_G1, 200, 256, 200, 40000, 51200, 51200, 1.f);
    k_gemm<0, false><<<dim3(4, 50, 1), 256>>>(p_G1, g2w, nullptr, p_X2, 3200, 256, 256, 0, 0, 0, 1.f);
    k_gemm<1, false><<<dim3(4, 4, 16), 256>>>(p_An, p_X2, g2b, p_G2, 200, 256, 200, 40000, 51200, 51200, 1.f);
    k_gemb<<<16, 256>>>();
    k_gemm<0, true><<<dim3(12, 1, 1), 256>>>(p_gemb, wih, bih, p_gi, 16, 768, 256, 0, 0, 0, 1.f);
    k_gru<<<1, 768>>>(whh, bhh, clsw, clsb, out);
    k_avgvar<<<157, 256>>>(out);
    k_varfin<<<1, 32>>>(out);
}

// round 15
// speedup vs baseline: 1.4749x; 1.0156x over previous
#include <cuda_runtime.h>
#include <math.h>

#define NWIN 3200
#define NEG9 -1000000000.0f

typedef unsigned long long ull;
#define PACKF2(out, lo, hi) asm("mov.b64 %0, {%1, %2};" : "=l"(out) : "f"(lo), "f"(hi))
#define UNPACKF2(lo, hi, in) asm("mov.b64 {%0, %1}, %2;" : "=f"(lo), "=f"(hi) : "l"(in))
#define FMAF2(d, a, b) asm("fma.rn.f32x2 %0, %1, %2, %0;" : "+l"(d) : "l"(a), "l"(b))

// ---------------- static scratch ----------------
__device__ float  d_c1max[NWIN*16*16*32];
__device__ float  d_c1min[NWIN*16*16*32];
__device__ float  d_c2max[NWIN*32*8*16];
__device__ float  d_c2min[NWIN*32*8*16];
__device__ float  d_feat[NWIN*32];
__device__ float  d_emb [NWIN*128];
__device__ float  d_Qm  [NWIN*128];
__device__ float  d_Km  [NWIN*128];
__device__ float  d_attn[16*200*200];
__device__ float  d_adj [16*200*200];
__device__ float  d_dinv[16*200];
__device__ float  d_An  [16*200*200];
__device__ float  d_X1  [NWIN*256];
__device__ float  d_G1  [NWIN*256];
__device__ float  d_X2  [NWIN*256];
__device__ float  d_G2  [NWIN*256];
__device__ float  d_gemb[16*256];
__device__ float  d_gi  [16*768];
__device__ double d_bnsum[96];
__device__ float  d_varpart[157];

__global__ void k_init(float* out){
    int t = threadIdx.x;
    if (t < 96) d_bnsum[t] = 0.0;
}

__global__ void k_noop(){}

// ---------------- fused CWT + conv1(1->16) + BN stats + coalesced pooled stores ----------------
__global__ void __launch_bounds__(256) k_cwtconv1(
        const float* __restrict__ x, const float* __restrict__ wr,
        const float* __restrict__ wi, const float* __restrict__ w,
        const float* __restrict__ b){
    __shared__ float xp[112];
    __shared__ float wrs[32*52], wis[32*52];
    __shared__ float sp[34*52];
    __shared__ float ssum[16], ssq[16];
    int n = blockIdx.x, tid = threadIdx.x;
    int lane = tid & 31, warp = tid >> 5;
    for (int i = tid; i < 112; i += 256){
        int s = i - 24;
        xp[i] = (s >= 0 && s < 50) ? x[n*50 + s] : 0.f;
    }
    for (int i = tid; i < 1600; i += 256){
        int f = i / 50, k = i % 50;
        wrs[f*52 + k] = wr[i];
        wis[f*52 + k] = wi[i];
    }
    for (int i = tid; i < 34*52; i += 256) sp[i] = 0.f;
    __syncthreads();

    {
        int f = tid >> 3, jb = (tid & 7) * 7;
        const float2* a2 = (const float2*)&wrs[f*52];
        const float2* b2 = (const float2*)&wis[f*52];
        float re[7] = {0,0,0,0,0,0,0}, im[7] = {0,0,0,0,0,0,0};
        float win[8];
        #pragma unroll
        for (int q = 0; q < 8; q++) win[q] = xp[jb + q];
        #pragma unroll
        for (int kk = 0; kk < 25; kk++){
            float2 wa = a2[kk], wb = b2[kk];
            #pragma unroll
            for (int q = 0; q < 7; q++){
                re[q] += win[q]*wa.x + win[q+1]*wa.y;
                im[q] += win[q]*wb.x + win[q+1]*wb.y;
            }
            #pragma unroll
            for (int q = 0; q < 6; q++) win[q] = win[q+2];
            win[6] = xp[jb + 2*kk + 8];
            win[7] = xp[jb + 2*kk + 9];
        }
        #pragma unroll
        for (int q = 0; q < 7; q++){
            int j = jb + q;
            if (j < 50) sp[(f+1)*52 + (j+1)] = sqrtf(re[q]*re[q] + im[q]*im[q]);
        }
    }
    __syncthreads();

    {
        bool act = lane < 25;
        #pragma unroll
        for (int cc = 0; cc < 2; cc++){
            int c = warp*2 + cc;
            float wl[9];
            #pragma unroll
            for (int k = 0; k < 9; k++) wl[k] = __ldg(&w[c*9 + k]);
            float bias = __ldg(&b[c]);
            float s = 0.f, sq = 0.f;
            for (int yp = 0; yp < 16; yp++){
                if (act){
                    const float* base = &sp[2*yp*52 + 2*lane];
                    float2 A0 = *(const float2*)(base);
                    float2 B0 = *(const float2*)(base + 2);
                    float2 A1 = *(const float2*)(base + 52);
                    float2 B1 = *(const float2*)(base + 54);
                    float2 A2 = *(const float2*)(base + 104);
                    float2 B2 = *(const float2*)(base + 106);
                    float2 A3 = *(const float2*)(base + 156);
                    float2 B3 = *(const float2*)(base + 158);
                    float v00 = bias + A0.x*wl[0] + A0.y*wl[1] + B0.x*wl[2]
                                     + A1.x*wl[3] + A1.y*wl[4] + B1.x*wl[5]
                                     + A2.x*wl[6] + A2.y*wl[7] + B2.x*wl[8];
                    float v01 = bias + A0.y*wl[0] + B0.x*wl[1] + B0.y*wl[2]
                                     + A1.y*wl[3] + B1.x*wl[4] + B1.y*wl[5]
                                     + A2.y*wl[6] + B2.x*wl[7] + B2.y*wl[8];
                    float v10 = bias + A1.x*wl[0] + A1.y*wl[1] + B1.x*wl[2]
                                     + A2.x*wl[3] + A2.y*wl[4] + B2.x*wl[5]
                                     + A3.x*wl[6] + A3.y*wl[7] + B3.x*wl[8];
                    float v11 = bias + A1.y*wl[0] + B1.x*wl[1] + B1.y*wl[2]
                                     + A2.y*wl[3] + B2.x*wl[4] + B2.y*wl[5]
                                     + A3.y*wl[6] + B3.x*wl[7] + B3.y*wl[8];
                    s  += v00 + v01 + v10 + v11;
                    sq += v00*v00 + v01*v01 + v10*v10 + v11*v11;
                    float mx = fmaxf(fmaxf(v00, v01), fmaxf(v10, v11));
                    float mn = fminf(fminf(v00, v01), fminf(v10, v11));
                    int row = ((n*16 + c)*16 + yp)*32;
                    d_c1max[row + lane] = mx;
                    d_c1min[row + lane] = mn;
                }
            }
            #pragma unroll
            for (int off = 16; off; off >>= 1){
                s  += __shfl_xor_sync(0xffffffffu, s,  off);
                sq += __shfl_xor_sync(0xffffffffu, sq, off);
            }
            if (lane == 0){ ssum[c] = s; ssq[c] = sq; }
        }
    }
    __syncthreads();
    if (tid < 16){
        atomicAdd(&d_bnsum[tid],      (double)ssum[tid]);
        atomicAdd(&d_bnsum[16 + tid], (double)ssq[tid]);
    }
}

// ---------------- conv2 (16->32): f32x2 packed FMA, fused BN1, deterministic ----------------
__global__ void __launch_bounds__(256) k_conv2(const float* __restrict__ w,
                                               const float* __restrict__ b,
                                               const float* __restrict__ g1,
                                               const float* __restrict__ b1){
    __shared__ float sp[16*504];
    __shared__ float psum[256], psq[256];
    __shared__ float ssc[16], ssh[16];
    int n = blockIdx.x, tid = threadIdx.x;
    if (tid < 16){
        double cnt = 5120000.0;
        double mu  = d_bnsum[tid] / cnt;
        double var = d_bnsum[16 + tid] / cnt - mu*mu;
        float sc = g1[tid] * rsqrtf((float)var + 1e-5f);
        ssc[tid] = sc;
        ssh[tid] = b1[tid] - (float)mu * sc;
    }
    for (int i = tid; i < 16*504; i += 256) sp[i] = 0.f;
    __syncthreads();
    for (int i = tid; i < 8192; i += 256){
        int xx = i & 31;
        if (xx < 25){
            int y = (i >> 5) & 15, ci = i >> 9;
            float sc = ssc[ci], sh = ssh[ci];
            float mx = d_c1max[n*8192 + i], mn = d_c1min[n*8192 + i];
            float v = fmaxf(sc * (sc >= 0.f ? mx : mn) + sh, 0.f);
            sp[ci*504 + (y+1)*28 + (xx+1)] = v;
        }
    }
    __syncthreads();

    int c = tid >> 3, yp = tid & 7;
    float bias = __ldg(&b[c]);
    ull accp0[12], accp1[12];
    ull bias2; PACKF2(bias2, bias, bias);
    #pragma unroll
    for (int m = 0; m < 12; m++){ accp0[m] = bias2; accp1[m] = bias2; }
    float acc0t = bias, acc1t = bias;

    for (int ci = 0; ci < 16; ci++){
        const float* wp = &w[(c*16 + ci)*9];
        float ws0=__ldg(wp+0),ws1=__ldg(wp+1),ws2=__ldg(wp+2),
              ws3=__ldg(wp+3),ws4=__ldg(wp+4),ws5=__ldg(wp+5),
              ws6=__ldg(wp+6),ws7=__ldg(wp+7),ws8=__ldg(wp+8);
        ull W0,W1,W2,W3,W4,W5,W6,W7,W8;
        PACKF2(W0,ws0,ws0); PACKF2(W1,ws1,ws1); PACKF2(W2,ws2,ws2);
        PACKF2(W3,ws3,ws3); PACKF2(W4,ws4,ws4); PACKF2(W5,ws5,ws5);
        PACKF2(W6,ws6,ws6); PACKF2(W7,ws7,ws7); PACKF2(W8,ws8,ws8);
        const float* r0 = &sp[ci*504 + (2*yp + 0)*28];
        const float* r1 = &sp[ci*504 + (2*yp + 1)*28];
        const float* r2 = &sp[ci*504 + (2*yp + 2)*28];
        const float* r3 = &sp[ci*504 + (2*yp + 3)*28];
        float2 A0 = *(const float2*)r0, A1 = *(const float2*)r1;
        float2 A2 = *(const float2*)r2, A3 = *(const float2*)r3;
        ull ap0,ap1,ap2,ap3;
        PACKF2(ap0,A0.x,A0.y); PACKF2(ap1,A1.x,A1.y);
        PACKF2(ap2,A2.x,A2.y); PACKF2(ap3,A3.x,A3.y);
        float ah0=A0.y, ah1=A1.y, ah2=A2.y, ah3=A3.y;
        #pragma unroll
        for (int m = 0; m < 12; m++){
            {
                float2 B = *(const float2*)&r0[2*m+2];
                ull bp, mp;
                PACKF2(bp, B.x, B.y);
                PACKF2(mp, ah0, B.x);
                FMAF2(accp0[m], ap0, W0);
                FMAF2(accp0[m], mp,  W1);
                FMAF2(accp0[m], bp,  W2);
                ap0 = bp; ah0 = B.y;
            }
            {
                float2 B = *(const float2*)&r1[2*m+2];
                ull bp, mp;
                PACKF2(bp, B.x, B.y);
                PACKF2(mp, ah1, B.x);
                FMAF2(accp0[m], ap1, W3); FMAF2(accp1[m], ap1, W0);
                FMAF2(accp0[m], mp,  W4); FMAF2(accp1[m], mp,  W1);
                FMAF2(accp0[m], bp,  W5); FMAF2(accp1[m], bp,  W2);
                ap1 = bp; ah1 = B.y;
            }
            {
                float2 B = *(const float2*)&r2[2*m+2];
                ull bp, mp;
                PACKF2(bp, B.x, B.y);
                PACKF2(mp, ah2, B.x);
                FMAF2(accp0[m], ap2, W6); FMAF2(accp1[m], ap2, W3);
                FMAF2(accp0[m], mp,  W7); FMAF2(accp1[m], mp,  W4);
                FMAF2(accp0[m], bp,  W8); FMAF2(accp1[m], bp,  W5);
                ap2 = bp; ah2 = B.y;
            }
            {
                float2 B = *(const float2*)&r3[2*m+2];
                ull bp, mp;
                PACKF2(bp, B.x, B.y);
                PACKF2(mp, ah3, B.x);
                FMAF2(accp1[m], ap3, W6);
                FMAF2(accp1[m], mp,  W7);
                FMAF2(accp1[m], bp,  W8);
                ap3 = bp; ah3 = B.y;
            }
        }
        float l0,h0,l1,h1,l2,h2,l3,h3;
        UNPACKF2(l0,h0,ap0); UNPACKF2(l1,h1,ap1);
        UNPACKF2(l2,h2,ap2); UNPACKF2(l3,h3,ap3);
        float e0=r0[26], e1=r1[26], e2=r2[26], e3=r3[26];
        acc0t += l0*ws0 + h0*ws1 + e0*ws2
               + l1*ws3 + h1*ws4 + e1*ws5
               + l2*ws6 + h2*ws7 + e2*ws8;
        acc1t += l1*ws0 + h1*ws1 + e1*ws2
               + l2*ws3 + h2*ws4 + e2*ws5
               + l3*ws6 + h3*ws7 + e3*ws8;
    }

    float a0[25], a1[25];
    #pragma unroll
    for (int m = 0; m < 12; m++){
        UNPACKF2(a0[2*m], a0[2*m+1], accp0[m]);
        UNPACKF2(a1[2*m], a1[2*m+1], accp1[m]);
    }
    a0[24] = acc0t; a1[24] = acc1t;

    float s = 0.f, sq = 0.f;
    #pragma unroll
    for (int xx = 0; xx < 25; xx++){
        s  += a0[xx] + a1[xx];
        sq += a0[xx]*a0[xx] + a1[xx]*a1[xx];
    }
    psum[tid] = s; psq[tid] = sq;
    __syncthreads();
    #pragma unroll
    for (int xq = 0; xq < 12; xq++){
        float m0 = fmaxf(a0[2*xq], a0[2*xq+1]);
        float m1 = fmaxf(a1[2*xq], a1[2*xq+1]);
        sp[tid*26 + xq] = fmaxf(m0, m1);
        float n0 = fminf(a0[2*xq], a0[2*xq+1]);
        float n1 = fminf(a1[2*xq], a1[2*xq+1]);
        sp[tid*26 + 13 + xq] = fminf(n0, n1);
    }
    if (tid < 32){
        float S = 0.f, Q = 0.f;
        #pragma unroll
        for (int q = 0; q < 8; q++){ S += psum[tid*8 + q]; Q += psq[tid*8 + q]; }
        atomicAdd(&d_bnsum[32 + tid], (double)S);
        atomicAdd(&d_bnsum[64 + tid], (double)Q);
    }
    __syncthreads();
    for (int j = tid; j < 4096; j += 256){
        int row = j >> 4, xq = j & 15;
        float vmax = 0.f, vmin = 0.f;
        if (xq < 12){
            vmax = sp[row*26 + xq];
            vmin = sp[row*26 + 13 + xq];
        }
        d_c2max[n*4096 + j] = vmax;
        d_c2min[n*4096 + j] = vmin;
    }
}

// ---------------- feat: fused BN2 + relu + spatial mean, deterministic ----------------
__global__ void __launch_bounds__(256) k_feat(const float* __restrict__ g2,
                                              const float* __restrict__ b2){
    __shared__ float ssc[32], ssh[32];
    __shared__ float rowsum[256];
    int n = blockIdx.x, tid = threadIdx.x;
    if (tid < 32){
        double cnt = 1280000.0;
        double mu  = d_bnsum[32 + tid] / cnt;
        double var = d_bnsum[64 + tid] / cnt - mu*mu;
        float sc = g2[tid] * rsqrtf((float)var + 1e-5f);
        ssc[tid] = sc;
        ssh[tid] = b2[tid] - (float)mu * sc;
    }
    __syncthreads();
    int x = tid & 15, rr = tid >> 4;
    for (int it = 0; it < 16; it++){
        int row = it*16 + rr;
        int c = row >> 3;
        float v = 0.f;
        if (x < 12){
            float sc = ssc[c], sh = ssh[c];
            float mx = d_c2max[(n*256 + row)*16 + x];
            float mn = d_c2min[(n*256 + row)*16 + x];
            float u = sc >= 0.f ? mx : mn;
            v = fmaxf(sc*u + sh, 0.f);
        }
        v += __shfl_xor_sync(0xffffffffu, v, 8);
        v += __shfl_xor_sync(0xffffffffu, v, 4);
        v += __shfl_xor_sync(0xffffffffu, v, 2);
        v += __shfl_xor_sync(0xffffffffu, v, 1);
        if (x == 0) rowsum[row] = v;
    }
    __syncthreads();
    if (tid < 32){
        float t = 0.f;
        #pragma unroll
        for (int q = 0; q < 8; q++) t += rowsum[tid*8 + q];
        d_feat[n*32 + tid] = t * (1.f/96.f);
    }
}

// ---------------- generic tiled SGEMM (64x64x16, 4x4 micro) ----------------
template<int ACT, bool TRANSB>
__global__ void __launch_bounds__(256) k_gemm(
        const float* __restrict__ A, const float* __restrict__ B,
        const float* __restrict__ bias, float* __restrict__ C,
        int M, int N, int Kd, int sA, int sB, int sC, float scale){
    __shared__ float As[16][68];
    __shared__ float Bs[16][68];
    int bz = blockIdx.z;
    A += (long)bz*sA; B += (long)bz*sB; C += (long)bz*sC;
    int tid = threadIdx.x;
    int tx = tid & 15, ty = tid >> 4;
    int row0 = blockIdx.y*64, col0 = blockIdx.x*64;
    float acc[4][4] = {};
    for (int k0 = 0; k0 < Kd; k0 += 16){
        #pragma unroll
        for (int l = 0; l < 4; l++){
            int idx = tid + l*256;
            int m = idx >> 4, k = idx & 15;
            int gm = row0 + m, gk = k0 + k;
            As[k][m] = (gm < M && gk < Kd) ? A[gm*Kd + gk] : 0.f;
        }
        #pragma unroll
        for (int l = 0; l < 4; l++){
            int idx = tid + l*256;
            if (TRANSB){
                int nn = idx >> 4, k = idx & 15;
                int gn = col0 + nn, gk = k0 + k;
                Bs[k][nn] = (gn < N && gk < Kd) ? B[gn*Kd + gk] : 0.f;
            } else {
                int k = idx >> 6, nn = idx & 63;
                int gn = col0 + nn, gk = k0 + k;
                Bs[k][nn] = (gn < N && gk < Kd) ? B[gk*N + gn] : 0.f;
            }
        }
        __syncthreads();
        #pragma unroll
        for (int k = 0; k < 16; k++){
            float4 av = *reinterpret_cast<const float4*>(&As[k][ty*4]);
            float4 bv = *reinterpret_cast<const float4*>(&Bs[k][tx*4]);
            float a[4] = {av.x, av.y, av.z, av.w};
            float bb[4] = {bv.x, bv.y, bv.z, bv.w};
            #pragma unroll
            for (int i = 0; i < 4; i++)
                #pragma unroll
                for (int j = 0; j < 4; j++)
                    acc[i][j] += a[i]*bb[j];
        }
        __syncthreads();
    }
    #pragma unroll
    for (int i = 0; i < 4; i++){
        int gm = row0 + ty*4 + i;
        if (gm >= M) continue;
        #pragma unroll
        for (int j = 0; j < 4; j++){
            int gn = col0 + tx*4 + j;
            if (gn >= N) continue;
            float v = acc[i][j]*scale;
            if (bias) v += bias[gn];
            if (ACT == 1) v = fmaxf(v, 0.f);
            if (ACT == 2) v = v > 0.f ? v : 0.2f*v;
            C[gm*N + gn] = v;
        }
    }
}

// ---------------- merged Q/K projection ----------------
__global__ void __launch_bounds__(256) k_gemmQK(
        const float* __restrict__ A,
        const float* __restrict__ qw, const float* __restrict__ qb,
        const float* __restrict__ kw, const float* __restrict__ kb,
        float* __restrict__ Qo, float* __restrict__ Ko){
    const float* B    = blockIdx.z ? kw : qw;
    const float* bias = blockIdx.z ? kb : qb;
    float*       C    = blockIdx.z ? Ko : Qo;
    __shared__ float As[16][68];
    __shared__ float Bs[16][68];
    int tid = threadIdx.x;
    int tx = tid & 15, ty = tid >> 4;
    int row0 = blockIdx.y*64, col0 = blockIdx.x*64;
    float acc[4][4] = {};
    for (int k0 = 0; k0 < 128; k0 += 16){
        #pragma unroll
        for (int l = 0; l < 4; l++){
            int idx = tid + l*256;
            int m = idx >> 4, k = idx & 15;
            As[k][m] = A[(row0 + m)*128 + k0 + k];
            Bs[k][m] = B[(col0 + m)*128 + k0 + k];
        }
        __syncthreads();
        #pragma unroll
        for (int k = 0; k < 16; k++){
            float4 av = *reinterpret_cast<const float4*>(&As[k][ty*4]);
            float4 bv = *reinterpret_cast<const float4*>(&Bs[k][tx*4]);
            float a[4] = {av.x, av.y, av.z, av.w};
            float bb[4] = {bv.x, bv.y, bv.z, bv.w};
            #pragma unroll
            for (int i = 0; i < 4; i++)
                #pragma unroll
                for (int j = 0; j < 4; j++)
                    acc[i][j] += a[i]*bb[j];
        }
        __syncthreads();
    }
    #pragma unroll
    for (int i = 0; i < 4; i++){
        int gm = row0 + ty*4 + i;
        #pragma unroll
        for (int j = 0; j < 4; j++){
            int gn = col0 + tx*4 + j;
            C[gm*128 + gn] = acc[i][j] + bias[gn];
        }
    }
}

// ---------------- top-K(20) mask + softmax per (t,r) row ----------------
__global__ void k_adj(){
    __shared__ float sa[200];
    __shared__ float red[256];
    int b = blockIdx.x, tid = threadIdx.x;
    int t = b / 200, r = b % 200;
    const float* row = &d_attn[(t*200 + r)*200];
    if (tid < 200) sa[tid] = row[tid];
    __syncthreads();
    float v = NEG9;
    if (tid < 200){
        float my = sa[tid];
        int cnt = 0;
        for (int j = 0; j < 200; j++){
            float aj = sa[j];
            cnt += (aj > my) || (aj == my && j < tid);
        }
        if (cnt < 20) v = (my == 0.f) ? NEG9 : my;
    }
    red[tid] = (tid < 200) ? v : NEG9;
    __syncthreads();
    for (int off = 128; off; off >>= 1){
        if (tid < off) red[tid] = fmaxf(red[tid], red[tid + off]);
        __syncthreads();
    }
    float m = red[0];
    __syncthreads();
    float e = (tid < 200) ? expf(v - m) : 0.f;
    red[tid] = e;
    __syncthreads();
    for (int off = 128; off; off >>= 1){
        if (tid < off) red[tid] += red[tid + off];
        __syncthreads();
    }
    float s = red[0];
    if (tid < 200) d_adj[(t*200 + r)*200 + tid] = e / s;
}

// ---------------- degree + dinv ----------------
__global__ void k_deg(){
    int t = blockIdx.x, s = threadIdx.x;
    if (s >= 200) return;
    const float* a = &d_adj[t*40000];
    float col = 0.f;
    for (int r = 0; r < 200; r++) col += a[r*200 + s];
    float diag = a[s*200 + s];
    float dsl = (diag == 0.f) ? 1.f : diag;
    float deg = col - diag + dsl;
    deg = (deg > 0.f) ? deg : 1.f;
    d_dinv[t*200 + s] = rsqrtf(deg);
}

// ---------------- An via 32x32 tile transpose ----------------
__global__ void k_An(){
    __shared__ float tile[32][33];
    int t = blockIdx.z;
    int r0 = blockIdx.x*32, s0 = blockIdx.y*32;
    int tx = threadIdx.x & 31, ty = threadIdx.x >> 5;
    const float* a = &d_adj[t*40000];
    #pragma unroll
    for (int q = 0; q < 4; q++){
        int s = s0 + ty + q*8, r = r0 + tx;
        if (s < 200 && r < 200) tile[ty + q*8][tx] = a[s*200 + r];
    }
    __syncthreads();
    #pragma unroll
    for (int q = 0; q < 4; q++){
        int r = r0 + ty + q*8, s = s0 + tx;
        if (r < 200 && s < 200){
            float val = tile[tx][ty + q*8];
            if (r == s) val = (val == 0.f) ? 1.f : val;
            d_An[(t*200 + r)*200 + s] = d_dinv[t*200 + r] * val * d_dinv[t*200 + s];
        }
    }
}

// ---------------- g_emb = mean over r ----------------
__global__ void k_gemb(){
    int t = blockIdx.x, h = threadIdx.x;
    float s = 0.f;
    #pragma unroll 4
    for (int r = 0; r < 200; r++) s += d_G2[(t*200 + r)*256 + h];
    d_gemb[t*256 + h] = s * (1.f/200.f);
}

// ---------------- GRU: 24-warp warp-per-row GEMV ----------------
__global__ void __launch_bounds__(768) k_gru(
        const float* __restrict__ whh, const float* __restrict__ bhh,
        const float* __restrict__ clsw, const float* __restrict__ clsb,
        float* out){
    __shared__ float hs[256];
    __shared__ float gh[768];
    int tid = threadIdx.x, lane = tid & 31, warp = tid >> 5;
    if (tid < 256) hs[tid] = 0.f;
    __syncthreads();
    for (int t = 0; t < 16; t++){
        #pragma unroll 4
        for (int rq = 0; rq < 32; rq++){
            int row = warp*32 + rq;
            const float4* wrow = (const float4*)(whh + row*256);
            float4 ha = ((const float4*)hs)[lane*2];
            float4 hb = ((const float4*)hs)[lane*2 + 1];
            float4 wa = __ldg(&wrow[lane*2]);
            float4 wb = __ldg(&wrow[lane*2 + 1]);
            float sum = wa.x*ha.x + wa.y*ha.y + wa.z*ha.z + wa.w*ha.w
                      + wb.x*hb.x + wb.y*hb.y + wb.z*hb.z + wb.w*hb.w;
            #pragma unroll
            for (int off = 16; off; off >>= 1)
                sum += __shfl_xor_sync(0xffffffffu, sum, off);
            if (lane == 0) gh[row] = sum + __ldg(&bhh[row]);
        }
        __syncthreads();
        if (tid < 256){
            int i = tid;
            float hr = gh[i], hz = gh[256 + i], hn = gh[512 + i];
            float gir = d_gi[t*768 + i], giz = d_gi[t*768 + 256 + i], gin = d_gi[t*768 + 512 + i];
            float rr = 1.f / (1.f + expf(-(gir + hr)));
            float z  = 1.f / (1.f + expf(-(giz + hz)));
            float nn = tanhf(gin + rr*hn);
            hs[i] = (1.f - z)*nn + z*hs[i];
        }
        __syncthreads();
    }
    if (tid < 2){
        float s = clsb[tid];
        for (int k = 0; k < 256; k++) s += clsw[tid*256 + k]*hs[k];
        out[tid] = s;
    }
}

// ---------------- avg_adj + edge variance (deterministic partials) ----------------
__global__ void k_avgvar(float* out){
    __shared__ float red[256];
    int idx = blockIdx.x*256 + threadIdx.x;
    float var = 0.f;
    if (idx < 40000){
        float x[16];
        float s = 0.f;
        #pragma unroll
        for (int t = 0; t < 16; t++){ x[t] = d_adj[t*40000 + idx]; s += x[t]; }
        float mu = s * (1.f/16.f);
        float ssd = 0.f;
        #pragma unroll
        for (int t = 0; t < 16; t++){ float d = x[t] - mu; ssd += d*d; }
        var = ssd * (1.f/15.f);
        out[2 + idx] = mu;
    }
    red[threadIdx.x] = var;
    __syncthreads();
    for (int off = 128; off; off >>= 1){
        if (threadIdx.x < off) red[threadIdx.x] += red[threadIdx.x + off];
        __syncthreads();
    }
    if (threadIdx.x == 0) d_varpart[blockIdx.x] = red[0];
}

__global__ void k_varfin(float* out){
    if (threadIdx.x == 0){
        float s = 0.f;
        for (int i = 0; i < 157; i++) s += d_varpart[i];
        out[40002] = s * (1.f/40000.f);
    }
}

// ---------------- driver ----------------
extern "C" void kernel_launch(void* const* d_in, const int* in_sizes, int n_in,
                              void* d_out, int out_size){
    const float* tw   = (const float*)d_in[0];
    const float* wavr = (const float*)d_in[1];
    const float* wavi = (const float*)d_in[2];
    const float* c1w  = (const float*)d_in[3];
    const float* c1b  = (const float*)d_in[4];
    const float* bn1g = (const float*)d_in[5];
    const float* bn1b = (const float*)d_in[6];
    const float* c2w  = (const float*)d_in[7];
    const float* c2b  = (const float*)d_in[8];
    const float* bn2g = (const float*)d_in[9];
    const float* bn2b = (const float*)d_in[10];
    const float* fcw  = (const float*)d_in[11];
    const float* fcb  = (const float*)d_in[12];
    const float* qw   = (const float*)d_in[13];
    const float* qb   = (const float*)d_in[14];
    const float* kw   = (const float*)d_in[15];
    const float* kb   = (const float*)d_in[16];
    const float* g1w  = (const float*)d_in[17];
    const float* g1b  = (const float*)d_in[18];
    const float* g2w  = (const float*)d_in[19];
    const float* g2b  = (const float*)d_in[20];
    const float* wih  = (const float*)d_in[21];
    const float* whh  = (const float*)d_in[22];
    const float* bih  = (const float*)d_in[23];
    const float* bhh  = (const float*)d_in[24];
    const float* clsw = (const float*)d_in[25];
    const float* clsb = (const float*)d_in[26];
    float* out = (float*)d_out;

    float *p_emb, *p_Q, *p_K, *p_attn, *p_An, *p_X1, *p_G1, *p_X2, *p_G2, *p_feat, *p_gemb, *p_gi;
    cudaGetSymbolAddress((void**)&p_emb,  d_emb);
    cudaGetSymbolAddress((void**)&p_Q,    d_Qm);
    cudaGetSymbolAddress((void**)&p_K,    d_Km);
    cudaGetSymbolAddress((void**)&p_attn, d_attn);
    cudaGetSymbolAddress((void**)&p_An,   d_An);
    cudaGetSymbolAddress((void**)&p_X1,   d_X1);
    cudaGetSymbolAddress((void**)&p_G1,   d_G1);
    cudaGetSymbolAddress((void**)&p_X2,   d_X2);
    cudaGetSymbolAddress((void**)&p_G2,   d_G2);
    cudaGetSymbolAddress((void**)&p_feat, d_feat);
    cudaGetSymbolAddress((void**)&p_gemb, d_gemb);
    cudaGetSymbolAddress((void**)&p_gi,   d_gi);

    k_init<<<1, 128>>>(out);        // 1
    k_noop<<<1, 32>>>();            // 2
    k_cwtconv1<<<NWIN, 256>>>(tw, wavr, wavi, c1w, c1b);   // 3
    k_conv2<<<NWIN, 256>>>(c2w, c2b, bn1g, bn1b);          // 4 <- profiled
    k_feat<<<NWIN, 256>>>(bn2g, bn2b);

    k_gemm<0, true><<<dim3(2, 50, 1), 256>>>(p_feat, fcw, fcb, p_emb, 3200, 128, 32, 0, 0, 0, 1.f);
    k_gemmQK<<<dim3(2, 50, 2), 256>>>(p_emb, qw, qb, kw, kb, p_Q, p_K);
    k_gemm<2, true><<<dim3(4, 4, 16), 256>>>(p_Q, p_K, nullptr, p_attn,
                                             200, 200, 128, 25600, 25600, 40000, 0.08838834764831845f);
    k_adj<<<3200, 256>>>();
    k_deg<<<16, 256>>>();
    k_An<<<dim3(7, 7, 16), 256>>>();
    k_gemm<0, false><<<dim3(4, 50, 1), 256>>>(p_emb, g1w, nullptr, p_X1, 3200, 256, 128, 0, 0, 0, 1.f);
    k_gemm<1, false><<<dim3(4, 4, 16), 256>>>(p_An, p_X1, g1b, p_G1, 200, 256, 200, 40000, 51200, 51200, 1.f);
    k_gemm<0, false><<<dim3(4, 50, 1), 256>>>(p_G1, g2w, nullptr, p_X2, 3200, 256, 256, 0, 0, 0, 1.f);
    k_gemm<1, false><<<dim3(4, 4, 16), 256>>>(p_An, p_X2, g2b, p_G2, 200, 256, 200, 40000, 51200, 51200, 1.f);
    k_gemb<<<16, 256>>>();
    k_gemm<0, true><<<dim3(12, 1, 1), 256>>>(p_gemb, wih, bih, p_gi, 16, 768, 256, 0, 0, 0, 1.f);
    k_gru<<<1, 768>>>(whh, bhh, clsw, clsb, out);
    k_avgvar<<<157, 256>>>(out);
    k_varfin<<<1, 32>>>(out);
}